// round 4
// baseline (speedup 1.0000x reference)
#include <cuda_runtime.h>
#include <cuda_bf16.h>
#include <math.h>

#define NN   20000
#define EE   320000
#define FIN  128
#define FH   256
#define RR   4
#define NH   4
#define CH   64
#define G3   (3*FH)

// ---------------- scratch: one pooled __device__ array, aliased ------------
// lifetimes:
//   agg  : RGCN1+RGCN2 (dead after RGCN2 gemm)        -> reused by gi
//   h1   : RGCN1 out, RGCN2 in (dead after RGCN2)     -> reused by gh
//   h2   : RGCN2 out, q/k/v/skip gemm in (dead after) -> reused by gh
//   q,k  : dead after k_score                          -> q reused by gh
//   v    : dead after k_attn
//   attn : alive through gi gemm
//   score: k_score..k_attn
#define OFF_AGG   ((size_t)0)
#define OFF_H1    (OFF_AGG  + (size_t)NN*RR*FH)     // 20.48M floats
#define OFF_H2    (OFF_H1   + (size_t)NN*FH)
#define OFF_Q     (OFF_H2   + (size_t)NN*FH)
#define OFF_K     (OFF_Q    + (size_t)NN*FH)
#define OFF_V     (OFF_K    + (size_t)NN*FH)
#define OFF_ATTN  (OFF_V    + (size_t)NN*FH)
#define OFF_SCORE (OFF_ATTN + (size_t)NN*FH)
#define POOL_SZ   (OFF_SCORE + (size_t)EE*NH)
#define OFF_GI    OFF_AGG                            // NN*G3=15.36M < 20.48M  (agg dead)
#define OFF_GH    OFF_H1                             // covers h1+h2+q=15.36M (all dead)

__device__ float g_pool[POOL_SZ];
__device__ float g_cnt[NN*RR];
__device__ int   g_smax[NN*NH];
__device__ float g_denom[NN*NH];

// ---------------- helpers --------------------------------------------------
__device__ __forceinline__ int f2oi(float f){ int i=__float_as_int(f); return i>=0 ? i : i^0x7fffffff; }
__device__ __forceinline__ float oi2f(int i){ return __int_as_float(i>=0 ? i : i^0x7fffffff); }
__device__ __forceinline__ float sigm(float x){ return 1.f/(1.f+expf(-x)); }

__global__ void k_zero_f(float* p, size_t n){
    for(size_t i=(size_t)blockIdx.x*blockDim.x+threadIdx.x; i<n; i+=(size_t)gridDim.x*blockDim.x) p[i]=0.f;
}
__global__ void k_init_attn_state(int* smax, float* denom, int n){
    int v = f2oi(-3.402823466e38f);
    for(int i=blockIdx.x*blockDim.x+threadIdx.x; i<n; i+=gridDim.x*blockDim.x){ smax[i]=v; denom[i]=0.f; }
}

// ---------------- edge kernels ---------------------------------------------
__global__ void k_count(const int* __restrict__ dst, const int* __restrict__ et, float* cnt, int E){
    for(int e=blockIdx.x*blockDim.x+threadIdx.x; e<E; e+=gridDim.x*blockDim.x)
        atomicAdd(&cnt[dst[e]*RR + et[e]], 1.f);
}

// warp per edge: agg[dst][etype][:] += x[src][:]
__global__ void k_scatter(const float* __restrict__ x, const int* __restrict__ src,
                          const int* __restrict__ dst, const int* __restrict__ et,
                          float* __restrict__ agg, int E, int F){
    int gtid = blockIdx.x*blockDim.x + threadIdx.x;
    int warp = gtid>>5, lane = gtid&31;
    int nw = (gridDim.x*blockDim.x)>>5;
    int F4 = F>>2;
    for(int e=warp; e<E; e+=nw){
        int s=src[e], d=dst[e], r=et[e];
        const float4* xs = (const float4*)(x + (size_t)s*F);
        float* ag = agg + ((size_t)d*RR + r)*F;
        for(int i=lane;i<F4;i+=32){
            float4 v = xs[i];
            atomicAdd(ag+4*i+0, v.x);
            atomicAdd(ag+4*i+1, v.y);
            atomicAdd(ag+4*i+2, v.z);
            atomicAdd(ag+4*i+3, v.w);
        }
    }
}

__global__ void k_norm(float* __restrict__ agg, const float* __restrict__ cnt, size_t total, int F){
    for(size_t i=(size_t)blockIdx.x*blockDim.x+threadIdx.x; i<total; i+=(size_t)gridDim.x*blockDim.x){
        size_t nr = i / (size_t)F;   // n*RR + r
        agg[i] *= 1.f / fmaxf(cnt[nr], 1.f);
    }
}

// warp per edge: per-head dot(q[dst], k[src]) / sqrt(C); record score + segment max
__global__ void k_score(const float* __restrict__ q, const float* __restrict__ kk,
                        const int* __restrict__ src, const int* __restrict__ dst,
                        float* __restrict__ score, int* __restrict__ smax, int E){
    int gtid = blockIdx.x*blockDim.x + threadIdx.x;
    int warp = gtid>>5, lane = gtid&31;
    int nw = (gridDim.x*blockDim.x)>>5;
    for(int e=warp; e<E; e+=nw){
        int s=src[e], d=dst[e];
        const float4* qd = (const float4*)(q  + (size_t)d*FH);
        const float4* ks = (const float4*)(kk + (size_t)s*FH);
        float4 a0=qd[lane],      b0=ks[lane];
        float4 a1=qd[lane+32],   b1=ks[lane+32];
        float p0 = a0.x*b0.x + a0.y*b0.y + a0.z*b0.z + a0.w*b0.w;  // head = lane/16
        float p1 = a1.x*b1.x + a1.y*b1.y + a1.z*b1.z + a1.w*b1.w;  // head = lane/16 + 2
        #pragma unroll
        for(int o=8;o>=1;o>>=1){
            p0 += __shfl_xor_sync(0xffffffffu, p0, o);
            p1 += __shfl_xor_sync(0xffffffffu, p1, o);
        }
        if((lane&15)==0){
            int h = lane>>4;  // 0 or 1
            float s0 = p0*0.125f, s1 = p1*0.125f;
            score[(size_t)e*NH + h]     = s0;
            score[(size_t)e*NH + h + 2] = s1;
            atomicMax(&smax[d*NH + h],     f2oi(s0));
            atomicMax(&smax[d*NH + h + 2], f2oi(s1));
        }
    }
}

// score -> exp(score - max); accumulate denom
__global__ void k_expsum(float* __restrict__ score, const int* __restrict__ dst,
                         const int* __restrict__ smax, float* __restrict__ denom, int E){
    int total = E*NH;
    for(int i=blockIdx.x*blockDim.x+threadIdx.x; i<total; i+=gridDim.x*blockDim.x){
        int e = i>>2, h = i&3;
        int d = dst[e];
        float m = oi2f(smax[d*NH + h]);
        float ex = expf(score[i]-m);
        score[i] = ex;
        atomicAdd(&denom[d*NH + h], ex);
    }
}

// warp per edge: out[dst] += alpha * v[src]
__global__ void k_attn(const float* __restrict__ score, const float* __restrict__ denom,
                       const float* __restrict__ v, const int* __restrict__ src,
                       const int* __restrict__ dst, float* __restrict__ out, int E){
    int gtid = blockIdx.x*blockDim.x + threadIdx.x;
    int warp = gtid>>5, lane = gtid&31;
    int nw = (gridDim.x*blockDim.x)>>5;
    for(int e=warp; e<E; e+=nw){
        int s=src[e], d=dst[e];
        int h0 = lane>>4;
        float a0 = score[(size_t)e*NH + h0]     / fmaxf(denom[d*NH + h0],     1e-16f);
        float a1 = score[(size_t)e*NH + h0 + 2] / fmaxf(denom[d*NH + h0 + 2], 1e-16f);
        const float4* vs = (const float4*)(v + (size_t)s*FH);
        float* od = out + (size_t)d*FH;
        float4 v0 = vs[lane];
        atomicAdd(od+4*lane+0,   a0*v0.x);
        atomicAdd(od+4*lane+1,   a0*v0.y);
        atomicAdd(od+4*lane+2,   a0*v0.z);
        atomicAdd(od+4*lane+3,   a0*v0.w);
        float4 v1 = vs[lane+32];
        atomicAdd(od+4*(lane+32)+0, a1*v1.x);
        atomicAdd(od+4*(lane+32)+1, a1*v1.y);
        atomicAdd(od+4*(lane+32)+2, a1*v1.z);
        atomicAdd(od+4*(lane+32)+3, a1*v1.w);
    }
}

// GRU gates
__global__ void k_gru(const float* __restrict__ gi, const float* __restrict__ gh,
                      const float* __restrict__ hprev, float* __restrict__ out){
    size_t total = (size_t)NN*FH;
    for(size_t i=(size_t)blockIdx.x*blockDim.x+threadIdx.x; i<total; i+=(size_t)gridDim.x*blockDim.x){
        size_t n = i/FH; int j = (int)(i%FH);
        const float* gin = gi + n*G3;
        const float* ghn = gh + n*G3;
        float r = sigm(gin[j]       + ghn[j]);
        float z = sigm(gin[FH+j]    + ghn[FH+j]);
        float nw = tanhf(gin[2*FH+j] + r*ghn[2*FH+j]);
        out[i] = (1.f - z)*nw + z*hprev[i];
    }
}

// ---------------- SGEMM: 128x128 block, 8x8/thread, BK=8 ------------------
// C[M,N] = A[M,K] @ op(B)  (+bias)(+=C)(relu)
// TRANSB=false: B is [K,N];  TRANSB=true: B is [N,K] (we multiply by B^T)
template<bool TRANSB>
__global__ void k_sgemm(const float* __restrict__ A, const float* __restrict__ B,
                        float* __restrict__ C, int M, int N, int K,
                        const float* __restrict__ bias, int accum, int relu)
{
    __shared__ float As[8][128];
    __shared__ float Bs[8][128];
    int tid = threadIdx.x;              // 256
    int m0 = blockIdx.y*128, n0 = blockIdx.x*128;
    int tr = tid>>4, tc = tid&15;       // 16x16 thread grid
    float acc[8][8];
    #pragma unroll
    for(int i=0;i<8;i++)
        #pragma unroll
        for(int j=0;j<8;j++) acc[i][j]=0.f;

    int la_m = tid>>1;                  // 0..127
    int la_k = (tid&1)*4;               // 0 or 4
    int lb_k = tid>>5;                  // 0..7 (non-trans)
    int lb_n = (tid&31)*4;

    for(int k0=0;k0<K;k0+=8){
        float4 av = make_float4(0.f,0.f,0.f,0.f);
        if(m0+la_m < M) av = *(const float4*)(A + (size_t)(m0+la_m)*K + k0 + la_k);
        As[la_k+0][la_m]=av.x; As[la_k+1][la_m]=av.y;
        As[la_k+2][la_m]=av.z; As[la_k+3][la_m]=av.w;
        if(TRANSB){
            // B[N,K]: Bs[k][n] = B[(n0+n)*K + k0+k]
            float4 bv = *(const float4*)(B + (size_t)(n0+la_m)*K + k0 + la_k);
            Bs[la_k+0][la_m]=bv.x; Bs[la_k+1][la_m]=bv.y;
            Bs[la_k+2][la_m]=bv.z; Bs[la_k+3][la_m]=bv.w;
        } else {
            float4 bv = *(const float4*)(B + (size_t)(k0+lb_k)*N + n0 + lb_n);
            *(float4*)&Bs[lb_k][lb_n] = bv;
        }
        __syncthreads();
        #pragma unroll
        for(int kkk=0;kkk<8;kkk++){
            float a[8], b[8];
            *(float4*)&a[0] = *(const float4*)&As[kkk][tr*8];
            *(float4*)&a[4] = *(const float4*)&As[kkk][tr*8+4];
            *(float4*)&b[0] = *(const float4*)&Bs[kkk][tc*8];
            *(float4*)&b[4] = *(const float4*)&Bs[kkk][tc*8+4];
            #pragma unroll
            for(int i=0;i<8;i++)
                #pragma unroll
                for(int j=0;j<8;j++)
                    acc[i][j] += a[i]*b[j];
        }
        __syncthreads();
    }
    #pragma unroll
    for(int i=0;i<8;i++){
        int row = m0 + tr*8 + i;
        if(row >= M) break;
        float* crow = C + (size_t)row*N + n0;
        #pragma unroll
        for(int j=0;j<8;j++){
            int col = tc*8 + j;
            float vv = acc[i][j];
            if(bias)  vv += bias[n0+col];
            if(accum) vv += crow[col];
            if(relu)  vv = fmaxf(vv, 0.f);
            crow[col] = vv;
        }
    }
}

// ---------------- host ------------------------------------------------------
extern "C" void kernel_launch(void* const* d_in, const int* in_sizes, int n_in,
                              void* d_out, int out_size)
{
    const float* x      = (const float*)d_in[0];
    const int*   eidx   = (const int*)  d_in[1];
    const int*   src    = eidx;
    const int*   dst    = eidx + EE;
    const int*   et     = (const int*)  d_in[2];
    const float* hprev  = (const float*)d_in[3];
    const float* W1     = (const float*)d_in[4];   // [R*IN, HID]
    const float* root1  = (const float*)d_in[5];
    const float* b1     = (const float*)d_in[6];
    const float* W2     = (const float*)d_in[7];   // [R*HID, HID]
    const float* root2  = (const float*)d_in[8];
    const float* b2     = (const float*)d_in[9];
    const float* Wq     = (const float*)d_in[10];
    const float* bq     = (const float*)d_in[11];
    const float* Wk     = (const float*)d_in[12];
    const float* bk     = (const float*)d_in[13];
    const float* Wv     = (const float*)d_in[14];
    const float* bv     = (const float*)d_in[15];
    const float* Wskip  = (const float*)d_in[16];
    const float* bskip  = (const float*)d_in[17];
    const float* W_ih   = (const float*)d_in[18];  // [3H, H]
    const float* b_ih   = (const float*)d_in[19];
    const float* W_hh   = (const float*)d_in[20];
    const float* b_hh   = (const float*)d_in[21];
    float* out = (float*)d_out;

    static float* pool = nullptr;
    static float* cnt; static int* smax; static float* denom;
    if(!pool){
        void* p;
        cudaGetSymbolAddress(&p, g_pool);  pool  = (float*)p;
        cudaGetSymbolAddress(&p, g_cnt);   cnt   = (float*)p;
        cudaGetSymbolAddress(&p, g_smax);  smax  = (int*)p;
        cudaGetSymbolAddress(&p, g_denom); denom = (float*)p;
    }
    float* agg   = pool + OFF_AGG;
    float* h1    = pool + OFF_H1;
    float* h2    = pool + OFF_H2;
    float* q     = pool + OFF_Q;
    float* k     = pool + OFF_K;
    float* v     = pool + OFF_V;
    float* attn  = pool + OFF_ATTN;
    float* score = pool + OFF_SCORE;
    float* gi    = pool + OFF_GI;   // aliases agg (dead by GRU stage)
    float* gh    = pool + OFF_GH;   // aliases h1/h2/q (dead by GRU stage)

    const int T = 256;
    dim3 g2((FH+127)/128,  (NN+127)/128);   // N=256
    dim3 g3((G3+127)/128,  (NN+127)/128);   // N=768
    int eWarps = (EE*32 + T-1)/T;           // 1 warp per edge

    // ---- counts (shared by both RGCN layers)
    k_zero_f<<<(NN*RR+T-1)/T, T>>>(cnt, (size_t)NN*RR);
    k_count <<<(EE+T-1)/T,    T>>>(dst, et, cnt, EE);

    // ---- RGCN layer 1
    k_zero_f<<<((size_t)NN*RR*FIN+T-1)/T, T>>>(agg, (size_t)NN*RR*FIN);
    k_scatter<<<eWarps, T>>>(x, src, dst, et, agg, EE, FIN);
    k_norm  <<<((size_t)NN*RR*FIN+T-1)/T, T>>>(agg, cnt, (size_t)NN*RR*FIN, FIN);
    k_sgemm<false><<<g2, T>>>(x,   root1, h1, NN, FH, FIN,    b1,     0, 0);
    k_sgemm<false><<<g2, T>>>(agg, W1,    h1, NN, FH, RR*FIN, nullptr,1, 1);

    // ---- RGCN layer 2
    k_zero_f<<<((size_t)NN*RR*FH+T-1)/T, T>>>(agg, (size_t)NN*RR*FH);
    k_scatter<<<eWarps, T>>>(h1, src, dst, et, agg, EE, FH);
    k_norm  <<<((size_t)NN*RR*FH+T-1)/T, T>>>(agg, cnt, (size_t)NN*RR*FH, FH);
    k_sgemm<false><<<g2, T>>>(h1,  root2, h2, NN, FH, FH,    b2,      0, 0);
    k_sgemm<false><<<g2, T>>>(agg, W2,    h2, NN, FH, RR*FH, nullptr, 1, 1);

    // ---- TransformerConv
    k_sgemm<false><<<g2, T>>>(h2, Wq,    q,    NN, FH, FH, bq,    0, 0);
    k_sgemm<false><<<g2, T>>>(h2, Wk,    k,    NN, FH, FH, bk,    0, 0);
    k_sgemm<false><<<g2, T>>>(h2, Wv,    v,    NN, FH, FH, bv,    0, 0);
    k_sgemm<false><<<g2, T>>>(h2, Wskip, attn, NN, FH, FH, bskip, 0, 0);  // skip seeds output
    k_init_attn_state<<<(NN*NH+T-1)/T, T>>>(smax, denom, NN*NH);
    k_score <<<eWarps, T>>>(q, k, src, dst, score, smax, EE);
    k_expsum<<<(EE*NH+T-1)/T, T>>>(score, dst, smax, denom, EE);
    k_attn  <<<eWarps, T>>>(score, denom, v, src, dst, attn, EE);

    // ---- GRU cell
    k_sgemm<true><<<g3, T>>>(attn,  W_ih, gi, NN, G3, FH, b_ih, 0, 0);
    k_sgemm<true><<<g3, T>>>(hprev, W_hh, gh, NN, G3, FH, b_hh, 0, 0);
    k_gru<<<((size_t)NN*FH+T-1)/T, T>>>(gi, gh, hprev, out);
}

// round 6
// speedup vs baseline: 1.0056x; 1.0056x over previous
#include <cuda_runtime.h>
#include <cuda_bf16.h>
#include <math.h>

#define NN   20000
#define EE   320000
#define FIN  128
#define FH   256
#define RR   4
#define NH   4
#define CH   64
#define G3   (3*FH)

// ---------------- scratch: one pooled __device__ array, aliased ------------
#define OFF_AGG   ((size_t)0)
#define OFF_H1    (OFF_AGG  + (size_t)NN*RR*FH)
#define OFF_H2    (OFF_H1   + (size_t)NN*FH)
#define OFF_Q     (OFF_H2   + (size_t)NN*FH)
#define OFF_K     (OFF_Q    + (size_t)NN*FH)
#define OFF_V     (OFF_K    + (size_t)NN*FH)
#define OFF_ATTN  (OFF_V    + (size_t)NN*FH)
#define OFF_SCORE (OFF_ATTN + (size_t)NN*FH)
#define POOL_SZ   (OFF_SCORE + (size_t)EE*NH)
#define OFF_GI    OFF_AGG                            // aliases agg (dead by GRU)
#define OFF_GH    OFF_H1                             // aliases h1/h2/q (dead by GRU)

__device__ float g_pool[POOL_SZ];
__device__ float g_cnt[NN*RR];
__device__ int   g_smax[NN*NH];
__device__ float g_denom[NN*NH];

// ---------------- helpers --------------------------------------------------
__device__ __forceinline__ int f2oi(float f){ int i=__float_as_int(f); return i>=0 ? i : i^0x7fffffff; }
__device__ __forceinline__ float oi2f(int i){ return __int_as_float(i>=0 ? i : i^0x7fffffff); }
__device__ __forceinline__ float sigm(float x){ return 1.f/(1.f+expf(-x)); }

__global__ void k_zero_f(float* p, size_t n){
    for(size_t i=(size_t)blockIdx.x*blockDim.x+threadIdx.x; i<n; i+=(size_t)gridDim.x*blockDim.x) p[i]=0.f;
}
__global__ void k_init_attn_state(int* smax, float* denom, int n){
    int v = f2oi(-3.402823466e38f);
    for(int i=blockIdx.x*blockDim.x+threadIdx.x; i<n; i+=gridDim.x*blockDim.x){ smax[i]=v; denom[i]=0.f; }
}

// ---------------- edge kernels ---------------------------------------------
__global__ void k_count(const int* __restrict__ dst, const int* __restrict__ et, float* cnt, int E){
    for(int e=blockIdx.x*blockDim.x+threadIdx.x; e<E; e+=gridDim.x*blockDim.x)
        atomicAdd(&cnt[dst[e]*RR + et[e]], 1.f);
}

__global__ void k_scatter(const float* __restrict__ x, const int* __restrict__ src,
                          const int* __restrict__ dst, const int* __restrict__ et,
                          float* __restrict__ agg, int E, int F){
    int gtid = blockIdx.x*blockDim.x + threadIdx.x;
    int warp = gtid>>5, lane = gtid&31;
    int nw = (gridDim.x*blockDim.x)>>5;
    int F4 = F>>2;
    for(int e=warp; e<E; e+=nw){
        int s=src[e], d=dst[e], r=et[e];
        const float4* xs = (const float4*)(x + (size_t)s*F);
        float* ag = agg + ((size_t)d*RR + r)*F;
        for(int i=lane;i<F4;i+=32){
            float4 v = xs[i];
            atomicAdd(ag+4*i+0, v.x);
            atomicAdd(ag+4*i+1, v.y);
            atomicAdd(ag+4*i+2, v.z);
            atomicAdd(ag+4*i+3, v.w);
        }
    }
}

__global__ void k_norm(float* __restrict__ agg, const float* __restrict__ cnt, size_t total, int F){
    for(size_t i=(size_t)blockIdx.x*blockDim.x+threadIdx.x; i<total; i+=(size_t)gridDim.x*blockDim.x){
        size_t nr = i / (size_t)F;
        agg[i] *= 1.f / fmaxf(cnt[nr], 1.f);
    }
}

__global__ void k_score(const float* __restrict__ q, const float* __restrict__ kk,
                        const int* __restrict__ src, const int* __restrict__ dst,
                        float* __restrict__ score, int* __restrict__ smax, int E){
    int gtid = blockIdx.x*blockDim.x + threadIdx.x;
    int warp = gtid>>5, lane = gtid&31;
    int nw = (gridDim.x*blockDim.x)>>5;
    for(int e=warp; e<E; e+=nw){
        int s=src[e], d=dst[e];
        const float4* qd = (const float4*)(q  + (size_t)d*FH);
        const float4* ks = (const float4*)(kk + (size_t)s*FH);
        float4 a0=qd[lane],      b0=ks[lane];
        float4 a1=qd[lane+32],   b1=ks[lane+32];
        float p0 = a0.x*b0.x + a0.y*b0.y + a0.z*b0.z + a0.w*b0.w;
        float p1 = a1.x*b1.x + a1.y*b1.y + a1.z*b1.z + a1.w*b1.w;
        #pragma unroll
        for(int o=8;o>=1;o>>=1){
            p0 += __shfl_xor_sync(0xffffffffu, p0, o);
            p1 += __shfl_xor_sync(0xffffffffu, p1, o);
        }
        if((lane&15)==0){
            int h = lane>>4;
            float s0 = p0*0.125f, s1 = p1*0.125f;
            score[(size_t)e*NH + h]     = s0;
            score[(size_t)e*NH + h + 2] = s1;
            atomicMax(&smax[d*NH + h],     f2oi(s0));
            atomicMax(&smax[d*NH + h + 2], f2oi(s1));
        }
    }
}

__global__ void k_expsum(float* __restrict__ score, const int* __restrict__ dst,
                         const int* __restrict__ smax, float* __restrict__ denom, int E){
    int total = E*NH;
    for(int i=blockIdx.x*blockDim.x+threadIdx.x; i<total; i+=gridDim.x*blockDim.x){
        int e = i>>2, h = i&3;
        int d = dst[e];
        float m = oi2f(smax[d*NH + h]);
        float ex = expf(score[i]-m);
        score[i] = ex;
        atomicAdd(&denom[d*NH + h], ex);
    }
}

__global__ void k_attn(const float* __restrict__ score, const float* __restrict__ denom,
                       const float* __restrict__ v, const int* __restrict__ src,
                       const int* __restrict__ dst, float* __restrict__ out, int E){
    int gtid = blockIdx.x*blockDim.x + threadIdx.x;
    int warp = gtid>>5, lane = gtid&31;
    int nw = (gridDim.x*blockDim.x)>>5;
    for(int e=warp; e<E; e+=nw){
        int s=src[e], d=dst[e];
        int h0 = lane>>4;
        float a0 = score[(size_t)e*NH + h0]     / fmaxf(denom[d*NH + h0],     1e-16f);
        float a1 = score[(size_t)e*NH + h0 + 2] / fmaxf(denom[d*NH + h0 + 2], 1e-16f);
        const float4* vs = (const float4*)(v + (size_t)s*FH);
        float* od = out + (size_t)d*FH;
        float4 v0 = vs[lane];
        atomicAdd(od+4*lane+0,   a0*v0.x);
        atomicAdd(od+4*lane+1,   a0*v0.y);
        atomicAdd(od+4*lane+2,   a0*v0.z);
        atomicAdd(od+4*lane+3,   a0*v0.w);
        float4 v1 = vs[lane+32];
        atomicAdd(od+4*(lane+32)+0, a1*v1.x);
        atomicAdd(od+4*(lane+32)+1, a1*v1.y);
        atomicAdd(od+4*(lane+32)+2, a1*v1.z);
        atomicAdd(od+4*(lane+32)+3, a1*v1.w);
    }
}

__global__ void k_gru(const float* __restrict__ gi, const float* __restrict__ gh,
                      const float* __restrict__ hprev, float* __restrict__ out){
    size_t total = (size_t)NN*FH;
    for(size_t i=(size_t)blockIdx.x*blockDim.x+threadIdx.x; i<total; i+=(size_t)gridDim.x*blockDim.x){
        size_t n = i/FH; int j = (int)(i%FH);
        const float* gin = gi + n*G3;
        const float* ghn = gh + n*G3;
        float r = sigm(gin[j]       + ghn[j]);
        float z = sigm(gin[FH+j]    + ghn[FH+j]);
        float nw = tanhf(gin[2*FH+j] + r*ghn[2*FH+j]);
        out[i] = (1.f - z)*nw + z*hprev[i];
    }
}

// ---------------- SGEMM: 128x128 block, 8x8/thread, BK=8, FFMA2 ------------
// C[M,N] = A[M,K] @ op(B)  (+bias)(+=C)(relu)
// Inner product uses packed fma.rn.f32x2 (sm_103a FFMA2): 2 fp32 FMA/lane/instr.
template<bool TRANSB>
__global__ void k_sgemm(const float* __restrict__ A, const float* __restrict__ B,
                        float* __restrict__ C, int M, int N, int K,
                        const float* __restrict__ bias, int accum, int relu)
{
    __shared__ float As[8][128];
    __shared__ float Bs[8][128];
    int tid = threadIdx.x;              // 256
    int m0 = blockIdx.y*128, n0 = blockIdx.x*128;
    int tr = tid>>4, tc = tid&15;       // 16x16 thread grid

    // acc2[i][j]: packed pair (col 2j, col 2j+1) of row i
    unsigned long long acc2[8][4];
    #pragma unroll
    for(int i=0;i<8;i++)
        #pragma unroll
        for(int j=0;j<4;j++) acc2[i][j]=0ull;

    int la_m = tid>>1;                  // 0..127
    int la_k = (tid&1)*4;               // 0 or 4
    int lb_k = tid>>5;                  // 0..7 (non-trans)
    int lb_n = (tid&31)*4;

    for(int k0=0;k0<K;k0+=8){
        float4 av = make_float4(0.f,0.f,0.f,0.f);
        if(m0+la_m < M) av = *(const float4*)(A + (size_t)(m0+la_m)*K + k0 + la_k);
        As[la_k+0][la_m]=av.x; As[la_k+1][la_m]=av.y;
        As[la_k+2][la_m]=av.z; As[la_k+3][la_m]=av.w;
        if(TRANSB){
            float4 bv = *(const float4*)(B + (size_t)(n0+la_m)*K + k0 + la_k);
            Bs[la_k+0][la_m]=bv.x; Bs[la_k+1][la_m]=bv.y;
            Bs[la_k+2][la_m]=bv.z; Bs[la_k+3][la_m]=bv.w;
        } else {
            float4 bv = *(const float4*)(B + (size_t)(k0+lb_k)*N + n0 + lb_n);
            *(float4*)&Bs[lb_k][lb_n] = bv;
        }
        __syncthreads();
        #pragma unroll
        for(int kkk=0;kkk<8;kkk++){
            float a[8];
            *(float4*)&a[0] = *(const float4*)&As[kkk][tr*8];
            *(float4*)&a[4] = *(const float4*)&As[kkk][tr*8+4];
            unsigned long long b2[4];
            const unsigned long long* bp = (const unsigned long long*)&Bs[kkk][tc*8];
            b2[0]=bp[0]; b2[1]=bp[1]; b2[2]=bp[2]; b2[3]=bp[3];
            #pragma unroll
            for(int i=0;i<8;i++){
                unsigned long long a2;
                asm("mov.b64 %0, {%1, %1};" : "=l"(a2) : "f"(a[i]));
                #pragma unroll
                for(int j=0;j<4;j++)
                    asm("fma.rn.f32x2 %0, %1, %2, %0;" : "+l"(acc2[i][j]) : "l"(a2), "l"(b2[j]));
            }
        }
        __syncthreads();
    }
    #pragma unroll
    for(int i=0;i<8;i++){
        int row = m0 + tr*8 + i;
        if(row >= M) break;
        float* crow = C + (size_t)row*N + n0;
        #pragma unroll
        for(int j=0;j<4;j++){
            float lo, hi;
            asm("mov.b64 {%0, %1}, %2;" : "=f"(lo), "=f"(hi) : "l"(acc2[i][j]));
            int c0 = tc*8 + 2*j;
            float v0 = lo, v1 = hi;
            if(bias){ v0 += bias[n0+c0]; v1 += bias[n0+c0+1]; }
            if(accum){ v0 += crow[c0]; v1 += crow[c0+1]; }
            if(relu){ v0 = fmaxf(v0,0.f); v1 = fmaxf(v1,0.f); }
            crow[c0]   = v0;
            crow[c0+1] = v1;
        }
    }
}

// ---------------- host ------------------------------------------------------
extern "C" void kernel_launch(void* const* d_in, const int* in_sizes, int n_in,
                              void* d_out, int out_size)
{
    const float* x      = (const float*)d_in[0];
    const int*   eidx   = (const int*)  d_in[1];
    const int*   src    = eidx;
    const int*   dst    = eidx + EE;
    const int*   et     = (const int*)  d_in[2];
    const float* hprev  = (const float*)d_in[3];
    const float* W1     = (const float*)d_in[4];
    const float* root1  = (const float*)d_in[5];
    const float* b1     = (const float*)d_in[6];
    const float* W2     = (const float*)d_in[7];
    const float* root2  = (const float*)d_in[8];
    const float* b2     = (const float*)d_in[9];
    const float* Wq     = (const float*)d_in[10];
    const float* bq     = (const float*)d_in[11];
    const float* Wk     = (const float*)d_in[12];
    const float* bk     = (const float*)d_in[13];
    const float* Wv     = (const float*)d_in[14];
    const float* bv     = (const float*)d_in[15];
    const float* Wskip  = (const float*)d_in[16];
    const float* bskip  = (const float*)d_in[17];
    const float* W_ih   = (const float*)d_in[18];
    const float* b_ih   = (const float*)d_in[19];
    const float* W_hh   = (const float*)d_in[20];
    const float* b_hh   = (const float*)d_in[21];
    float* out = (float*)d_out;

    static float* pool = nullptr;
    static float* cnt; static int* smax; static float* denom;
    if(!pool){
        void* p;
        cudaGetSymbolAddress(&p, g_pool);  pool  = (float*)p;
        cudaGetSymbolAddress(&p, g_cnt);   cnt   = (float*)p;
        cudaGetSymbolAddress(&p, g_smax);  smax  = (int*)p;
        cudaGetSymbolAddress(&p, g_denom); denom = (float*)p;
    }
    float* agg   = pool + OFF_AGG;
    float* h1    = pool + OFF_H1;
    float* h2    = pool + OFF_H2;
    float* q     = pool + OFF_Q;
    float* k     = pool + OFF_K;
    float* v     = pool + OFF_V;
    float* attn  = pool + OFF_ATTN;
    float* score = pool + OFF_SCORE;
    float* gi    = pool + OFF_GI;
    float* gh    = pool + OFF_GH;

    const int T = 256;
    dim3 g2((FH+127)/128,  (NN+127)/128);
    dim3 g3((G3+127)/128,  (NN+127)/128);
    int eWarps = (EE*32 + T-1)/T;

    // ---- counts (shared by both RGCN layers)
    k_zero_f<<<(NN*RR+T-1)/T, T>>>(cnt, (size_t)NN*RR);
    k_count <<<(EE+T-1)/T,    T>>>(dst, et, cnt, EE);

    // ---- RGCN layer 1
    k_zero_f<<<((size_t)NN*RR*FIN+T-1)/T, T>>>(agg, (size_t)NN*RR*FIN);
    k_scatter<<<eWarps, T>>>(x, src, dst, et, agg, EE, FIN);
    k_norm  <<<((size_t)NN*RR*FIN+T-1)/T, T>>>(agg, cnt, (size_t)NN*RR*FIN, FIN);
    k_sgemm<false><<<g2, T>>>(x,   root1, h1, NN, FH, FIN,    b1,     0, 0);
    k_sgemm<false><<<g2, T>>>(agg, W1,    h1, NN, FH, RR*FIN, nullptr,1, 1);

    // ---- RGCN layer 2
    k_zero_f<<<((size_t)NN*RR*FH+T-1)/T, T>>>(agg, (size_t)NN*RR*FH);
    k_scatter<<<eWarps, T>>>(h1, src, dst, et, agg, EE, FH);
    k_norm  <<<((size_t)NN*RR*FH+T-1)/T, T>>>(agg, cnt, (size_t)NN*RR*FH, FH);
    k_sgemm<false><<<g2, T>>>(h1,  root2, h2, NN, FH, FH,    b2,      0, 0);
    k_sgemm<false><<<g2, T>>>(agg, W2,    h2, NN, FH, RR*FH, nullptr, 1, 1);

    // ---- TransformerConv
    k_sgemm<false><<<g2, T>>>(h2, Wq,    q,    NN, FH, FH, bq,    0, 0);
    k_sgemm<false><<<g2, T>>>(h2, Wk,    k,    NN, FH, FH, bk,    0, 0);
    k_sgemm<false><<<g2, T>>>(h2, Wv,    v,    NN, FH, FH, bv,    0, 0);
    k_sgemm<false><<<g2, T>>>(h2, Wskip, attn, NN, FH, FH, bskip, 0, 0);
    k_init_attn_state<<<(NN*NH+T-1)/T, T>>>(smax, denom, NN*NH);
    k_score <<<eWarps, T>>>(q, k, src, dst, score, smax, EE);
    k_expsum<<<(EE*NH+T-1)/T, T>>>(score, dst, smax, denom, EE);
    k_attn  <<<eWarps, T>>>(score, denom, v, src, dst, attn, EE);

    // ---- GRU cell
    k_sgemm<true><<<g3, T>>>(attn,  W_ih, gi, NN, G3, FH, b_ih, 0, 0);
    k_sgemm<true><<<g3, T>>>(hprev, W_hh, gh, NN, G3, FH, b_hh, 0, 0);
    k_gru<<<((size_t)NN*FH+T-1)/T, T>>>(gi, gh, hprev, out);
}

// round 7
// speedup vs baseline: 1.1782x; 1.1716x over previous
#include <cuda_runtime.h>
#include <cuda_bf16.h>
#include <math.h>

#define NN   20000
#define EE   320000
#define FIN  128
#define FH   256
#define RR   4
#define NH   4
#define CH   64
#define G3   (3*FH)

// ---------------- scratch: one pooled __device__ array, aliased ------------
#define OFF_AGG   ((size_t)0)
#define OFF_H1    (OFF_AGG  + (size_t)NN*RR*FH)
#define OFF_H2    (OFF_H1   + (size_t)NN*FH)
#define OFF_Q     (OFF_H2   + (size_t)NN*FH)
#define OFF_K     (OFF_Q    + (size_t)NN*FH)
#define OFF_V     (OFF_K    + (size_t)NN*FH)
#define OFF_ATTN  (OFF_V    + (size_t)NN*FH)
#define OFF_SCORE (OFF_ATTN + (size_t)NN*FH)
#define POOL_SZ   (OFF_SCORE + (size_t)EE*NH)
#define OFF_GI    OFF_AGG                            // aliases agg (dead by GRU)
#define OFF_GH    OFF_H1                             // aliases h1/h2/q (dead by GRU)

__device__ float g_pool[POOL_SZ];
__device__ float g_cnt[NN*RR];
__device__ int   g_smax[NN*NH];
__device__ float g_denom[NN*NH];

// ---------------- helpers --------------------------------------------------
__device__ __forceinline__ int f2oi(float f){ int i=__float_as_int(f); return i>=0 ? i : i^0x7fffffff; }
__device__ __forceinline__ float oi2f(int i){ return __int_as_float(i>=0 ? i : i^0x7fffffff); }
__device__ __forceinline__ float sigm(float x){ return 1.f/(1.f+expf(-x)); }

__global__ void k_zero_f(float* p, size_t n){
    for(size_t i=(size_t)blockIdx.x*blockDim.x+threadIdx.x; i<n; i+=(size_t)gridDim.x*blockDim.x) p[i]=0.f;
}
__global__ void k_init_attn_state(int* smax, float* denom, int n){
    int v = f2oi(-3.402823466e38f);
    for(int i=blockIdx.x*blockDim.x+threadIdx.x; i<n; i+=gridDim.x*blockDim.x){ smax[i]=v; denom[i]=0.f; }
}

// ---------------- edge kernels ---------------------------------------------
__global__ void k_count(const int* __restrict__ dst, const int* __restrict__ et, float* cnt, int E){
    for(int e=blockIdx.x*blockDim.x+threadIdx.x; e<E; e+=gridDim.x*blockDim.x)
        atomicAdd(&cnt[dst[e]*RR + et[e]], 1.f);
}

__global__ void k_scatter(const float* __restrict__ x, const int* __restrict__ src,
                          const int* __restrict__ dst, const int* __restrict__ et,
                          float* __restrict__ agg, int E, int F){
    int gtid = blockIdx.x*blockDim.x + threadIdx.x;
    int warp = gtid>>5, lane = gtid&31;
    int nw = (gridDim.x*blockDim.x)>>5;
    int F4 = F>>2;
    for(int e=warp; e<E; e+=nw){
        int s=src[e], d=dst[e], r=et[e];
        const float4* xs = (const float4*)(x + (size_t)s*F);
        float* ag = agg + ((size_t)d*RR + r)*F;
        for(int i=lane;i<F4;i+=32){
            float4 v = xs[i];
            atomicAdd(ag+4*i+0, v.x);
            atomicAdd(ag+4*i+1, v.y);
            atomicAdd(ag+4*i+2, v.z);
            atomicAdd(ag+4*i+3, v.w);
        }
    }
}

__global__ void k_norm(float* __restrict__ agg, const float* __restrict__ cnt, size_t total, int F){
    for(size_t i=(size_t)blockIdx.x*blockDim.x+threadIdx.x; i<total; i+=(size_t)gridDim.x*blockDim.x){
        size_t nr = i / (size_t)F;
        agg[i] *= 1.f / fmaxf(cnt[nr], 1.f);
    }
}

__global__ void k_score(const float* __restrict__ q, const float* __restrict__ kk,
                        const int* __restrict__ src, const int* __restrict__ dst,
                        float* __restrict__ score, int* __restrict__ smax, int E){
    int gtid = blockIdx.x*blockDim.x + threadIdx.x;
    int warp = gtid>>5, lane = gtid&31;
    int nw = (gridDim.x*blockDim.x)>>5;
    for(int e=warp; e<E; e+=nw){
        int s=src[e], d=dst[e];
        const float4* qd = (const float4*)(q  + (size_t)d*FH);
        const float4* ks = (const float4*)(kk + (size_t)s*FH);
        float4 a0=qd[lane],      b0=ks[lane];
        float4 a1=qd[lane+32],   b1=ks[lane+32];
        float p0 = a0.x*b0.x + a0.y*b0.y + a0.z*b0.z + a0.w*b0.w;
        float p1 = a1.x*b1.x + a1.y*b1.y + a1.z*b1.z + a1.w*b1.w;
        #pragma unroll
        for(int o=8;o>=1;o>>=1){
            p0 += __shfl_xor_sync(0xffffffffu, p0, o);
            p1 += __shfl_xor_sync(0xffffffffu, p1, o);
        }
        if((lane&15)==0){
            int h = lane>>4;
            float s0 = p0*0.125f, s1 = p1*0.125f;
            score[(size_t)e*NH + h]     = s0;
            score[(size_t)e*NH + h + 2] = s1;
            atomicMax(&smax[d*NH + h],     f2oi(s0));
            atomicMax(&smax[d*NH + h + 2], f2oi(s1));
        }
    }
}

__global__ void k_expsum(float* __restrict__ score, const int* __restrict__ dst,
                         const int* __restrict__ smax, float* __restrict__ denom, int E){
    int total = E*NH;
    for(int i=blockIdx.x*blockDim.x+threadIdx.x; i<total; i+=gridDim.x*blockDim.x){
        int e = i>>2, h = i&3;
        int d = dst[e];
        float m = oi2f(smax[d*NH + h]);
        float ex = expf(score[i]-m);
        score[i] = ex;
        atomicAdd(&denom[d*NH + h], ex);
    }
}

__global__ void k_attn(const float* __restrict__ score, const float* __restrict__ denom,
                       const float* __restrict__ v, const int* __restrict__ src,
                       const int* __restrict__ dst, float* __restrict__ out, int E){
    int gtid = blockIdx.x*blockDim.x + threadIdx.x;
    int warp = gtid>>5, lane = gtid&31;
    int nw = (gridDim.x*blockDim.x)>>5;
    for(int e=warp; e<E; e+=nw){
        int s=src[e], d=dst[e];
        int h0 = lane>>4;
        float a0 = score[(size_t)e*NH + h0]     / fmaxf(denom[d*NH + h0],     1e-16f);
        float a1 = score[(size_t)e*NH + h0 + 2] / fmaxf(denom[d*NH + h0 + 2], 1e-16f);
        const float4* vs = (const float4*)(v + (size_t)s*FH);
        float* od = out + (size_t)d*FH;
        float4 v0 = vs[lane];
        atomicAdd(od+4*lane+0,   a0*v0.x);
        atomicAdd(od+4*lane+1,   a0*v0.y);
        atomicAdd(od+4*lane+2,   a0*v0.z);
        atomicAdd(od+4*lane+3,   a0*v0.w);
        float4 v1 = vs[lane+32];
        atomicAdd(od+4*(lane+32)+0, a1*v1.x);
        atomicAdd(od+4*(lane+32)+1, a1*v1.y);
        atomicAdd(od+4*(lane+32)+2, a1*v1.z);
        atomicAdd(od+4*(lane+32)+3, a1*v1.w);
    }
}

__global__ void k_gru(const float* __restrict__ gi, const float* __restrict__ gh,
                      const float* __restrict__ hprev, float* __restrict__ out){
    size_t total = (size_t)NN*FH;
    for(size_t i=(size_t)blockIdx.x*blockDim.x+threadIdx.x; i<total; i+=(size_t)gridDim.x*blockDim.x){
        size_t n = i/FH; int j = (int)(i%FH);
        const float* gin = gi + n*G3;
        const float* ghn = gh + n*G3;
        float r = sigm(gin[j]       + ghn[j]);
        float z = sigm(gin[FH+j]    + ghn[FH+j]);
        float nw = tanhf(gin[2*FH+j] + r*ghn[2*FH+j]);
        out[i] = (1.f - z)*nw + z*hprev[i];
    }
}

// ---- SGEMM: 128x128 block, 8x8/thread, BK=16, double-buffered, FFMA2 ------
// C[M,N] = A[M,K] @ op(B)  (+bias)(+=C)(relu)
// TRANSB=false: B is [K,N];  TRANSB=true: B is [N,K] (multiply by B^T).
// Mainloop: prefetch next K-tile's LDGs, compute current from smem, STS, 1 bar.
template<bool TRANSB>
__global__ __launch_bounds__(256, 2)
void k_sgemm(const float* __restrict__ A, const float* __restrict__ B,
             float* __restrict__ C, int M, int N, int K,
             const float* __restrict__ bias, int accum, int relu)
{
    __shared__ float As[2][16][128];
    __shared__ float Bs[2][16][128];
    const int tid = threadIdx.x;              // 256
    const int m0 = blockIdx.y*128, n0 = blockIdx.x*128;
    const int tr = tid>>4, tc = tid&15;       // 16x16 thread grid

    unsigned long long acc2[8][4];            // packed col pairs
    #pragma unroll
    for(int i=0;i<8;i++)
        #pragma unroll
        for(int j=0;j<4;j++) acc2[i][j]=0ull;

    const int la_m = tid>>1;                  // 0..127 (A row / TRANSB-B row)
    const int la_k = (tid&1)*8;               // 0 or 8 (two float4 at +0,+4)
    const int lb_k = tid>>5;                  // 0..7 (non-trans B rows, +8 second)
    const int lb_n = (tid&31)*4;

    const bool a_ok = (m0+la_m < M);
    const float* Arow = A + (size_t)(m0+la_m)*K + la_k;
    const float* Brow_t = TRANSB ? (B + (size_t)(n0+la_m)*K + la_k) : nullptr;

    float4 ra0, ra1, rb0, rb1;
    // ---- load tile k0 into registers
    #define LOAD_TILE(k0)                                                        \
        do{                                                                      \
            if(a_ok){ ra0 = *(const float4*)(Arow + (k0));                       \
                      ra1 = *(const float4*)(Arow + (k0) + 4); }                 \
            else    { ra0 = make_float4(0,0,0,0); ra1 = ra0; }                   \
            if(TRANSB){                                                          \
                rb0 = *(const float4*)(Brow_t + (k0));                           \
                rb1 = *(const float4*)(Brow_t + (k0) + 4);                       \
            } else {                                                             \
                rb0 = *(const float4*)(B + (size_t)((k0)+lb_k  )*N + n0 + lb_n); \
                rb1 = *(const float4*)(B + (size_t)((k0)+lb_k+8)*N + n0 + lb_n); \
            }                                                                    \
        }while(0)

    #define STORE_TILE(buf)                                                      \
        do{                                                                      \
            As[buf][la_k+0][la_m]=ra0.x; As[buf][la_k+1][la_m]=ra0.y;            \
            As[buf][la_k+2][la_m]=ra0.z; As[buf][la_k+3][la_m]=ra0.w;            \
            As[buf][la_k+4][la_m]=ra1.x; As[buf][la_k+5][la_m]=ra1.y;            \
            As[buf][la_k+6][la_m]=ra1.z; As[buf][la_k+7][la_m]=ra1.w;            \
            if(TRANSB){                                                          \
                Bs[buf][la_k+0][la_m]=rb0.x; Bs[buf][la_k+1][la_m]=rb0.y;        \
                Bs[buf][la_k+2][la_m]=rb0.z; Bs[buf][la_k+3][la_m]=rb0.w;        \
                Bs[buf][la_k+4][la_m]=rb1.x; Bs[buf][la_k+5][la_m]=rb1.y;        \
                Bs[buf][la_k+6][la_m]=rb1.z; Bs[buf][la_k+7][la_m]=rb1.w;        \
            } else {                                                             \
                *(float4*)&Bs[buf][lb_k  ][lb_n] = rb0;                          \
                *(float4*)&Bs[buf][lb_k+8][lb_n] = rb1;                          \
            }                                                                    \
        }while(0)

    #define COMPUTE(buf)                                                         \
        do{                                                                      \
            _Pragma("unroll")                                                    \
            for(int kkk=0;kkk<16;kkk++){                                         \
                float a[8];                                                      \
                *(float4*)&a[0] = *(const float4*)&As[buf][kkk][tr*8];           \
                *(float4*)&a[4] = *(const float4*)&As[buf][kkk][tr*8+4];         \
                unsigned long long b2[4];                                        \
                const unsigned long long* bp =                                   \
                    (const unsigned long long*)&Bs[buf][kkk][tc*8];              \
                b2[0]=bp[0]; b2[1]=bp[1]; b2[2]=bp[2]; b2[3]=bp[3];              \
                _Pragma("unroll")                                                \
                for(int i=0;i<8;i++){                                            \
                    unsigned long long a2;                                       \
                    asm("mov.b64 %0, {%1, %1};" : "=l"(a2) : "f"(a[i]));         \
                    _Pragma("unroll")                                            \
                    for(int j=0;j<4;j++)                                         \
                        asm("fma.rn.f32x2 %0, %1, %2, %0;"                       \
                            : "+l"(acc2[i][j]) : "l"(a2), "l"(b2[j]));           \
                }                                                                \
            }                                                                    \
        }while(0)

    LOAD_TILE(0);
    STORE_TILE(0);
    __syncthreads();
    int buf = 0;
    for(int k0=16; k0<K; k0+=16){
        LOAD_TILE(k0);        // LDGs in flight while computing current buffer
        COMPUTE(buf);
        STORE_TILE(buf^1);
        __syncthreads();
        buf ^= 1;
    }
    COMPUTE(buf);

    #undef LOAD_TILE
    #undef STORE_TILE
    #undef COMPUTE

    #pragma unroll
    for(int i=0;i<8;i++){
        int row = m0 + tr*8 + i;
        if(row >= M) break;
        float* crow = C + (size_t)row*N + n0;
        #pragma unroll
        for(int j=0;j<4;j++){
            float lo, hi;
            asm("mov.b64 {%0, %1}, %2;" : "=f"(lo), "=f"(hi) : "l"(acc2[i][j]));
            int c0 = tc*8 + 2*j;
            float v0 = lo, v1 = hi;
            if(bias){ v0 += bias[n0+c0]; v1 += bias[n0+c0+1]; }
            if(accum){ v0 += crow[c0]; v1 += crow[c0+1]; }
            if(relu){ v0 = fmaxf(v0,0.f); v1 = fmaxf(v1,0.f); }
            crow[c0]   = v0;
            crow[c0+1] = v1;
        }
    }
}

// ---------------- host ------------------------------------------------------
extern "C" void kernel_launch(void* const* d_in, const int* in_sizes, int n_in,
                              void* d_out, int out_size)
{
    const float* x      = (const float*)d_in[0];
    const int*   eidx   = (const int*)  d_in[1];
    const int*   src    = eidx;
    const int*   dst    = eidx + EE;
    const int*   et     = (const int*)  d_in[2];
    const float* hprev  = (const float*)d_in[3];
    const float* W1     = (const float*)d_in[4];
    const float* root1  = (const float*)d_in[5];
    const float* b1     = (const float*)d_in[6];
    const float* W2     = (const float*)d_in[7];
    const float* root2  = (const float*)d_in[8];
    const float* b2     = (const float*)d_in[9];
    const float* Wq     = (const float*)d_in[10];
    const float* bq     = (const float*)d_in[11];
    const float* Wk     = (const float*)d_in[12];
    const float* bk     = (const float*)d_in[13];
    const float* Wv     = (const float*)d_in[14];
    const float* bv     = (const float*)d_in[15];
    const float* Wskip  = (const float*)d_in[16];
    const float* bskip  = (const float*)d_in[17];
    const float* W_ih   = (const float*)d_in[18];
    const float* b_ih   = (const float*)d_in[19];
    const float* W_hh   = (const float*)d_in[20];
    const float* b_hh   = (const float*)d_in[21];
    float* out = (float*)d_out;

    static float* pool = nullptr;
    static float* cnt; static int* smax; static float* denom;
    if(!pool){
        void* p;
        cudaGetSymbolAddress(&p, g_pool);  pool  = (float*)p;
        cudaGetSymbolAddress(&p, g_cnt);   cnt   = (float*)p;
        cudaGetSymbolAddress(&p, g_smax);  smax  = (int*)p;
        cudaGetSymbolAddress(&p, g_denom); denom = (float*)p;
    }
    float* agg   = pool + OFF_AGG;
    float* h1    = pool + OFF_H1;
    float* h2    = pool + OFF_H2;
    float* q     = pool + OFF_Q;
    float* k     = pool + OFF_K;
    float* v     = pool + OFF_V;
    float* attn  = pool + OFF_ATTN;
    float* score = pool + OFF_SCORE;
    float* gi    = pool + OFF_GI;
    float* gh    = pool + OFF_GH;

    const int T = 256;
    dim3 g2((FH+127)/128,  (NN+127)/128);
    dim3 g3((G3+127)/128,  (NN+127)/128);
    int eWarps = (EE*32 + T-1)/T;

    // ---- counts (shared by both RGCN layers)
    k_zero_f<<<(NN*RR+T-1)/T, T>>>(cnt, (size_t)NN*RR);
    k_count <<<(EE+T-1)/T,    T>>>(dst, et, cnt, EE);

    // ---- RGCN layer 1
    k_zero_f<<<((size_t)NN*RR*FIN+T-1)/T, T>>>(agg, (size_t)NN*RR*FIN);
    k_scatter<<<eWarps, T>>>(x, src, dst, et, agg, EE, FIN);
    k_norm  <<<((size_t)NN*RR*FIN+T-1)/T, T>>>(agg, cnt, (size_t)NN*RR*FIN, FIN);
    k_sgemm<false><<<g2, T>>>(x,   root1, h1, NN, FH, FIN,    b1,     0, 0);
    k_sgemm<false><<<g2, T>>>(agg, W1,    h1, NN, FH, RR*FIN, nullptr,1, 1);

    // ---- RGCN layer 2
    k_zero_f<<<((size_t)NN*RR*FH+T-1)/T, T>>>(agg, (size_t)NN*RR*FH);
    k_scatter<<<eWarps, T>>>(h1, src, dst, et, agg, EE, FH);
    k_norm  <<<((size_t)NN*RR*FH+T-1)/T, T>>>(agg, cnt, (size_t)NN*RR*FH, FH);
    k_sgemm<false><<<g2, T>>>(h1,  root2, h2, NN, FH, FH,    b2,      0, 0);
    k_sgemm<false><<<g2, T>>>(agg, W2,    h2, NN, FH, RR*FH, nullptr, 1, 1);

    // ---- TransformerConv
    k_sgemm<false><<<g2, T>>>(h2, Wq,    q,    NN, FH, FH, bq,    0, 0);
    k_sgemm<false><<<g2, T>>>(h2, Wk,    k,    NN, FH, FH, bk,    0, 0);
    k_sgemm<false><<<g2, T>>>(h2, Wv,    v,    NN, FH, FH, bv,    0, 0);
    k_sgemm<false><<<g2, T>>>(h2, Wskip, attn, NN, FH, FH, bskip, 0, 0);
    k_init_attn_state<<<(NN*NH+T-1)/T, T>>>(smax, denom, NN*NH);
    k_score <<<eWarps, T>>>(q, k, src, dst, score, smax, EE);
    k_expsum<<<(EE*NH+T-1)/T, T>>>(score, dst, smax, denom, EE);
    k_attn  <<<eWarps, T>>>(score, denom, v, src, dst, attn, EE);

    // ---- GRU cell
    k_sgemm<true><<<g3, T>>>(attn,  W_ih, gi, NN, G3, FH, b_ih, 0, 0);
    k_sgemm<true><<<g3, T>>>(hprev, W_hh, gh, NN, G3, FH, b_hh, 0, 0);
    k_gru<<<((size_t)NN*FH+T-1)/T, T>>>(gi, gh, hprev, out);
}

// round 8
// speedup vs baseline: 1.3016x; 1.1047x over previous
#include <cuda_runtime.h>
#include <cuda_bf16.h>
#include <math.h>

#define NN   20000
#define EE   320000
#define FIN  128
#define FH   256
#define RR   4
#define NH   4
#define G3   (3*FH)

// ---------------- scratch pool (aliased lifetimes) --------------------------
#define OFF_AGG   ((size_t)0)
#define OFF_H1    (OFF_AGG  + (size_t)NN*RR*FH)
#define OFF_H2    (OFF_H1   + (size_t)NN*FH)
#define OFF_Q     (OFF_H2   + (size_t)NN*FH)
#define OFF_K     (OFF_Q    + (size_t)NN*FH)
#define OFF_V     (OFF_K    + (size_t)NN*FH)
#define OFF_ATTN  (OFF_V    + (size_t)NN*FH)
#define OFF_SCORE (OFF_ATTN + (size_t)NN*FH)
#define OFF_GHX   (OFF_SCORE+ (size_t)EE*NH)
#define POOL_SZ   (OFF_GHX  + (size_t)NN*G3)
#define OFF_GI    OFF_AGG                       // aliases agg (dead by GRU)

__device__ float g_pool[POOL_SZ];
__device__ float g_cnt[NN*RR];
__device__ int   g_smax[NN*NH];
__device__ float g_denom[NN*NH];
__device__ int   g_ticks[4];

// ---------------- helpers ---------------------------------------------------
__device__ __forceinline__ int f2oi(float f){ int i=__float_as_int(f); return i>=0 ? i : i^0x7fffffff; }
__device__ __forceinline__ float oi2f(int i){ return __int_as_float(i>=0 ? i : i^0x7fffffff); }
__device__ __forceinline__ float sigm(float x){ return 1.f/(1.f+expf(-x)); }
__device__ __forceinline__ float4 f4relu(float4 v){ return make_float4(fmaxf(v.x,0.f),fmaxf(v.y,0.f),fmaxf(v.z,0.f),fmaxf(v.w,0.f)); }
__device__ __forceinline__ float4 f4scale(float4 v, float s){ return make_float4(v.x*s,v.y*s,v.z*s,v.w*s); }

__global__ void k_zero_f(float* p, size_t n){
    for(size_t i=(size_t)blockIdx.x*blockDim.x+threadIdx.x; i<n; i+=(size_t)gridDim.x*blockDim.x) p[i]=0.f;
}
__global__ void k_tick0(){ if(threadIdx.x<4) g_ticks[threadIdx.x]=0; }
__global__ void k_seed_bias(float* C, const float* bias, int M, int N){
    size_t total=(size_t)M*N;
    for(size_t i=(size_t)blockIdx.x*blockDim.x+threadIdx.x; i<total; i+=(size_t)gridDim.x*blockDim.x)
        C[i]=bias[i%(size_t)N];
}
__global__ void k_init_attn_state(int* smax, float* denom, int n){
    int v = f2oi(-3.402823466e38f);
    for(int i=blockIdx.x*blockDim.x+threadIdx.x; i<n; i+=gridDim.x*blockDim.x){ smax[i]=v; denom[i]=0.f; }
}

// ---------------- edge kernels ----------------------------------------------
__global__ void k_count(const int* __restrict__ dst, const int* __restrict__ et, float* cnt, int E){
    for(int e=blockIdx.x*blockDim.x+threadIdx.x; e<E; e+=gridDim.x*blockDim.x)
        atomicAdd(&cnt[dst[e]*RR + et[e]], 1.f);
}

__global__ void k_scatter(const float* __restrict__ x, const int* __restrict__ src,
                          const int* __restrict__ dst, const int* __restrict__ et,
                          float* __restrict__ agg, int E, int F, int relu){
    int gtid = blockIdx.x*blockDim.x + threadIdx.x;
    int warp = gtid>>5, lane = gtid&31;
    int nw = (gridDim.x*blockDim.x)>>5;
    int F4 = F>>2;
    for(int e=warp; e<E; e+=nw){
        int s=src[e], d=dst[e], r=et[e];
        const float4* xs = (const float4*)(x + (size_t)s*F);
        float* ag = agg + ((size_t)d*RR + r)*F;
        for(int i=lane;i<F4;i+=32){
            float4 v = xs[i];
            if(relu) v = f4relu(v);
            atomicAdd(ag+4*i+0, v.x);
            atomicAdd(ag+4*i+1, v.y);
            atomicAdd(ag+4*i+2, v.z);
            atomicAdd(ag+4*i+3, v.w);
        }
    }
}

__global__ void k_score(const float* __restrict__ q, const float* __restrict__ kk,
                        const int* __restrict__ src, const int* __restrict__ dst,
                        float* __restrict__ score, int* __restrict__ smax, int E){
    int gtid = blockIdx.x*blockDim.x + threadIdx.x;
    int warp = gtid>>5, lane = gtid&31;
    int nw = (gridDim.x*blockDim.x)>>5;
    for(int e=warp; e<E; e+=nw){
        int s=src[e], d=dst[e];
        const float4* qd = (const float4*)(q  + (size_t)d*FH);
        const float4* ks = (const float4*)(kk + (size_t)s*FH);
        float4 a0=qd[lane],      b0=ks[lane];
        float4 a1=qd[lane+32],   b1=ks[lane+32];
        float p0 = a0.x*b0.x + a0.y*b0.y + a0.z*b0.z + a0.w*b0.w;
        float p1 = a1.x*b1.x + a1.y*b1.y + a1.z*b1.z + a1.w*b1.w;
        #pragma unroll
        for(int o=8;o>=1;o>>=1){
            p0 += __shfl_xor_sync(0xffffffffu, p0, o);
            p1 += __shfl_xor_sync(0xffffffffu, p1, o);
        }
        if((lane&15)==0){
            int h = lane>>4;
            float s0 = p0*0.125f, s1 = p1*0.125f;
            score[(size_t)e*NH + h]     = s0;
            score[(size_t)e*NH + h + 2] = s1;
            atomicMax(&smax[d*NH + h],     f2oi(s0));
            atomicMax(&smax[d*NH + h + 2], f2oi(s1));
        }
    }
}

__global__ void k_expsum(float* __restrict__ score, const int* __restrict__ dst,
                         const int* __restrict__ smax, float* __restrict__ denom, int E){
    int total = E*NH;
    for(int i=blockIdx.x*blockDim.x+threadIdx.x; i<total; i+=gridDim.x*blockDim.x){
        int e = i>>2, h = i&3;
        int d = dst[e];
        float m = oi2f(smax[d*NH + h]);
        float ex = expf(score[i]-m);
        score[i] = ex;
        atomicAdd(&denom[d*NH + h], ex);
    }
}

__global__ void k_attn(const float* __restrict__ score, const float* __restrict__ denom,
                       const float* __restrict__ v, const int* __restrict__ src,
                       const int* __restrict__ dst, float* __restrict__ out, int E){
    int gtid = blockIdx.x*blockDim.x + threadIdx.x;
    int warp = gtid>>5, lane = gtid&31;
    int nw = (gridDim.x*blockDim.x)>>5;
    for(int e=warp; e<E; e+=nw){
        int s=src[e], d=dst[e];
        int h0 = lane>>4;
        float a0 = score[(size_t)e*NH + h0]     / fmaxf(denom[d*NH + h0],     1e-16f);
        float a1 = score[(size_t)e*NH + h0 + 2] / fmaxf(denom[d*NH + h0 + 2], 1e-16f);
        const float4* vs = (const float4*)(v + (size_t)s*FH);
        float* od = out + (size_t)d*FH;
        float4 v0 = vs[lane];
        atomicAdd(od+4*lane+0,   a0*v0.x);
        atomicAdd(od+4*lane+1,   a0*v0.y);
        atomicAdd(od+4*lane+2,   a0*v0.z);
        atomicAdd(od+4*lane+3,   a0*v0.w);
        float4 v1 = vs[lane+32];
        atomicAdd(od+4*(lane+32)+0, a1*v1.x);
        atomicAdd(od+4*(lane+32)+1, a1*v1.y);
        atomicAdd(od+4*(lane+32)+2, a1*v1.z);
        atomicAdd(od+4*(lane+32)+3, a1*v1.w);
    }
}

__global__ void k_gru(const float* __restrict__ gi, const float* __restrict__ gh,
                      const float* __restrict__ hprev, float* __restrict__ out){
    size_t total = (size_t)NN*FH;
    for(size_t i=(size_t)blockIdx.x*blockDim.x+threadIdx.x; i<total; i+=(size_t)gridDim.x*blockDim.x){
        size_t n = i/FH; int j = (int)(i%FH);
        const float* gin = gi + n*G3;
        const float* ghn = gh + n*G3;
        float r = sigm(gin[j]       + ghn[j]);
        float z = sigm(gin[FH+j]    + ghn[FH+j]);
        float nw = tanhf(gin[2*FH+j] + r*ghn[2*FH+j]);
        out[i] = (1.f - z)*nw + z*hprev[i];
    }
}

// ---------------- batched persistent SGEMM ----------------------------------
// Tiles: 128x128, 256 threads, 8x8/thread, BK=16 double-buffered, FFMA2.
// Entry modes: mode 0=plain A, 1=relu(A), 2=A scaled by 1/max(cnt[row*RR+rr],1).
// Epilogue: atomic_ep ? atomicAdd into C (pre-seeded) : store C = acc + bias.
struct Entry {
    const float* A; const float* B; const float* bias; const float* cnt;
    float* C;
    int M, N, K, lda, ldb;
    int transB, atomic_ep, mode, rr;
    int tiles_n, ntiles;
};
struct Batch { int ng; int total; int slot; Entry e[6]; };

__global__ __launch_bounds__(256, 2)
void k_bgemm(Batch bt)
{
    __shared__ float As[2][16][128];
    __shared__ float Bs[2][16][128];
    __shared__ int s_t;
    const int tid = threadIdx.x;
    const int tr = tid>>4, tc = tid&15;
    const int la_m = tid>>1, la_k = (tid&1)*8;
    const int lb_k = tid>>5, lb_n = (tid&31)*4;

    for(;;){
        if(tid==0) s_t = atomicAdd(&g_ticks[bt.slot], 1);
        __syncthreads();
        int t = s_t;
        if(t >= bt.total) return;

        int g=0, base=0;
        while(t >= base + bt.e[g].ntiles){ base += bt.e[g].ntiles; g++; }
        const Entry E = bt.e[g];
        int lt = t - base;
        int tm = lt / E.tiles_n, tn = lt - tm*E.tiles_n;
        int m0 = tm*128, n0 = tn*128;

        unsigned long long acc2[8][4];
        #pragma unroll
        for(int i=0;i<8;i++)
            #pragma unroll
            for(int j=0;j<4;j++) acc2[i][j]=0ull;

        const bool a_ok = (m0+la_m < E.M);
        const float* Arow   = E.A + (size_t)(m0+la_m)*E.lda + la_k;
        const float* Brow_t = E.B + (size_t)(n0+la_m)*E.ldb + la_k;
        float ascale = 1.f;
        if(E.mode==2 && a_ok) ascale = 1.f/fmaxf(E.cnt[(m0+la_m)*RR + E.rr], 1.f);

        float4 ra0, ra1, rb0, rb1;
        #define LOAD_TILE(k0)                                                          \
            do{                                                                        \
                if(a_ok){ ra0 = *(const float4*)(Arow + (k0));                         \
                          ra1 = *(const float4*)(Arow + (k0) + 4);                     \
                          if(E.mode==1){ ra0=f4relu(ra0); ra1=f4relu(ra1); }           \
                          else if(E.mode==2){ ra0=f4scale(ra0,ascale);                 \
                                              ra1=f4scale(ra1,ascale); } }            \
                else    { ra0 = make_float4(0,0,0,0); ra1 = ra0; }                     \
                if(E.transB){                                                          \
                    rb0 = *(const float4*)(Brow_t + (k0));                             \
                    rb1 = *(const float4*)(Brow_t + (k0) + 4);                         \
                } else {                                                               \
                    rb0 = *(const float4*)(E.B + (size_t)((k0)+lb_k  )*E.ldb + n0+lb_n); \
                    rb1 = *(const float4*)(E.B + (size_t)((k0)+lb_k+8)*E.ldb + n0+lb_n); \
                }                                                                      \
            }while(0)

        #define STORE_TILE(buf)                                                        \
            do{                                                                        \
                As[buf][la_k+0][la_m]=ra0.x; As[buf][la_k+1][la_m]=ra0.y;              \
                As[buf][la_k+2][la_m]=ra0.z; As[buf][la_k+3][la_m]=ra0.w;              \
                As[buf][la_k+4][la_m]=ra1.x; As[buf][la_k+5][la_m]=ra1.y;              \
                As[buf][la_k+6][la_m]=ra1.z; As[buf][la_k+7][la_m]=ra1.w;              \
                if(E.transB){                                                          \
                    Bs[buf][la_k+0][la_m]=rb0.x; Bs[buf][la_k+1][la_m]=rb0.y;          \
                    Bs[buf][la_k+2][la_m]=rb0.z; Bs[buf][la_k+3][la_m]=rb0.w;          \
                    Bs[buf][la_k+4][la_m]=rb1.x; Bs[buf][la_k+5][la_m]=rb1.y;          \
                    Bs[buf][la_k+6][la_m]=rb1.z; Bs[buf][la_k+7][la_m]=rb1.w;          \
                } else {                                                               \
                    *(float4*)&Bs[buf][lb_k  ][lb_n] = rb0;                            \
                    *(float4*)&Bs[buf][lb_k+8][lb_n] = rb1;                            \
                }                                                                      \
            }while(0)

        #define COMPUTE(buf)                                                           \
            do{                                                                        \
                _Pragma("unroll")                                                      \
                for(int kkk=0;kkk<16;kkk++){                                           \
                    float a[8];                                                        \
                    *(float4*)&a[0] = *(const float4*)&As[buf][kkk][tr*8];             \
                    *(float4*)&a[4] = *(const float4*)&As[buf][kkk][tr*8+4];           \
                    unsigned long long b2[4];                                          \
                    const unsigned long long* bp =                                     \
                        (const unsigned long long*)&Bs[buf][kkk][tc*8];                \
                    b2[0]=bp[0]; b2[1]=bp[1]; b2[2]=bp[2]; b2[3]=bp[3];                \
                    _Pragma("unroll")                                                  \
                    for(int i=0;i<8;i++){                                              \
                        unsigned long long a2;                                         \
                        asm("mov.b64 %0, {%1, %1};" : "=l"(a2) : "f"(a[i]));           \
                        _Pragma("unroll")                                              \
                        for(int j=0;j<4;j++)                                           \
                            asm("fma.rn.f32x2 %0, %1, %2, %0;"                         \
                                : "+l"(acc2[i][j]) : "l"(a2), "l"(b2[j]));             \
                    }                                                                  \
                }                                                                      \
            }while(0)

        LOAD_TILE(0);
        STORE_TILE(0);
        __syncthreads();
        int buf = 0;
        for(int k0=16; k0<E.K; k0+=16){
            LOAD_TILE(k0);
            COMPUTE(buf);
            STORE_TILE(buf^1);
            __syncthreads();
            buf ^= 1;
        }
        COMPUTE(buf);
        #undef LOAD_TILE
        #undef STORE_TILE
        #undef COMPUTE

        #pragma unroll
        for(int i=0;i<8;i++){
            int row = m0 + tr*8 + i;
            if(row >= E.M) break;
            float* crow = E.C + (size_t)row*E.N + n0;
            #pragma unroll
            for(int j=0;j<4;j++){
                float lo, hi;
                asm("mov.b64 {%0, %1}, %2;" : "=f"(lo), "=f"(hi) : "l"(acc2[i][j]));
                int c0 = tc*8 + 2*j;
                if(E.atomic_ep){
                    atomicAdd(crow+c0,   lo);
                    atomicAdd(crow+c0+1, hi);
                } else {
                    crow[c0]   = lo + E.bias[n0+c0];
                    crow[c0+1] = hi + E.bias[n0+c0+1];
                }
            }
        }
        __syncthreads();   // protect smem + s_t before next ticket
    }
}

// ---------------- host ------------------------------------------------------
static Entry mkent(const float* A, int lda, const float* B, int ldb, int transB,
                   float* C, const float* bias, int M, int N, int K,
                   int atomic_ep, int mode, int rr, const float* cnt){
    Entry e;
    e.A=A; e.B=B; e.bias=bias; e.cnt=cnt; e.C=C;
    e.M=M; e.N=N; e.K=K; e.lda=lda; e.ldb=ldb;
    e.transB=transB; e.atomic_ep=atomic_ep; e.mode=mode; e.rr=rr;
    e.tiles_n = N/128;
    e.ntiles  = ((M+127)/128) * e.tiles_n;
    return e;
}

extern "C" void kernel_launch(void* const* d_in, const int* in_sizes, int n_in,
                              void* d_out, int out_size)
{
    const float* x      = (const float*)d_in[0];
    const int*   eidx   = (const int*)  d_in[1];
    const int*   src    = eidx;
    const int*   dst    = eidx + EE;
    const int*   et     = (const int*)  d_in[2];
    const float* hprev  = (const float*)d_in[3];
    const float* W1     = (const float*)d_in[4];
    const float* root1  = (const float*)d_in[5];
    const float* b1     = (const float*)d_in[6];
    const float* W2     = (const float*)d_in[7];
    const float* root2  = (const float*)d_in[8];
    const float* b2     = (const float*)d_in[9];
    const float* Wq     = (const float*)d_in[10];
    const float* bq     = (const float*)d_in[11];
    const float* Wk     = (const float*)d_in[12];
    const float* bk     = (const float*)d_in[13];
    const float* Wv     = (const float*)d_in[14];
    const float* bv     = (const float*)d_in[15];
    const float* Wskip  = (const float*)d_in[16];
    const float* bskip  = (const float*)d_in[17];
    const float* W_ih   = (const float*)d_in[18];
    const float* b_ih   = (const float*)d_in[19];
    const float* W_hh   = (const float*)d_in[20];
    const float* b_hh   = (const float*)d_in[21];
    float* out = (float*)d_out;

    static float* pool = nullptr;
    static float* cnt; static int* smax; static float* denom;
    if(!pool){
        void* p;
        cudaGetSymbolAddress(&p, g_pool);  pool  = (float*)p;
        cudaGetSymbolAddress(&p, g_cnt);   cnt   = (float*)p;
        cudaGetSymbolAddress(&p, g_smax);  smax  = (int*)p;
        cudaGetSymbolAddress(&p, g_denom); denom = (float*)p;
    }
    float* agg   = pool + OFF_AGG;
    float* h1    = pool + OFF_H1;
    float* h2    = pool + OFF_H2;
    float* q     = pool + OFF_Q;
    float* k     = pool + OFF_K;
    float* v     = pool + OFF_V;
    float* attn  = pool + OFF_ATTN;
    float* score = pool + OFF_SCORE;
    float* gh    = pool + OFF_GHX;
    float* gi    = pool + OFF_GI;

    const int T = 256;
    const int GB = 304;                 // persistent gemm blocks (2 x 152 SMs)
    int eWarps = (EE*32 + T-1)/T;

    k_tick0<<<1,32>>>();

    // ---- counts
    k_zero_f<<<(NN*RR+T-1)/T, T>>>(cnt, (size_t)NN*RR);
    k_count <<<(EE+T-1)/T,    T>>>(dst, et, cnt, EE);

    // ---- RGCN layer 1 scatter (no norm kernel; folded into gemm A-load)
    k_zero_f<<<((size_t)NN*RR*FIN+T-1)/T, T>>>(agg, (size_t)NN*RR*FIN);
    k_scatter<<<eWarps, T>>>(x, src, dst, et, agg, EE, FIN, 0);
    k_seed_bias<<<1024, T>>>(h1, b1, NN, FH);

    // Batch 1: RGCN1 (root + 4 relation K-chunks, atomic) + gh gemm (independent)
    {
        Batch bt; bt.slot=0; bt.ng=6;
        bt.e[0]=mkent(x,   FIN,  root1,          FH, 0, h1, nullptr, NN, FH, FIN, 1, 0, 0, nullptr);
        for(int r=0;r<RR;r++)
            bt.e[1+r]=mkent(agg + r*FIN, RR*FIN, W1 + (size_t)r*FIN*FH, FH, 0,
                            h1, nullptr, NN, FH, FIN, 1, 2, r, cnt);
        bt.e[5]=mkent(hprev, FH, W_hh, FH, 1, gh, b_hh, NN, G3, FH, 0, 0, 0, nullptr);
        bt.total=0; for(int i=0;i<bt.ng;i++) bt.total += bt.e[i].ntiles;
        k_bgemm<<<GB, T>>>(bt);
    }

    // ---- RGCN layer 2 scatter (reads relu(h1))
    k_zero_f<<<((size_t)NN*RR*FH+T-1)/T, T>>>(agg, (size_t)NN*RR*FH);
    k_scatter<<<eWarps, T>>>(h1, src, dst, et, agg, EE, FH, 1);
    k_seed_bias<<<1024, T>>>(h2, b2, NN, FH);

    // Batch 2: RGCN2 (root reads relu(h1); 4 relation chunks, all atomic)
    {
        Batch bt; bt.slot=1; bt.ng=5;
        bt.e[0]=mkent(h1, FH, root2, FH, 0, h2, nullptr, NN, FH, FH, 1, 1, 0, nullptr);
        for(int r=0;r<RR;r++)
            bt.e[1+r]=mkent(agg + r*FH, RR*FH, W2 + (size_t)r*FH*FH, FH, 0,
                            h2, nullptr, NN, FH, FH, 1, 2, r, cnt);
        bt.total=0; for(int i=0;i<bt.ng;i++) bt.total += bt.e[i].ntiles;
        k_bgemm<<<GB, T>>>(bt);
    }

    // Batch 3: q/k/v/skip (A = relu(h2))
    {
        Batch bt; bt.slot=2; bt.ng=4;
        bt.e[0]=mkent(h2, FH, Wq,    FH, 0, q,    bq,    NN, FH, FH, 0, 1, 0, nullptr);
        bt.e[1]=mkent(h2, FH, Wk,    FH, 0, k,    bk,    NN, FH, FH, 0, 1, 0, nullptr);
        bt.e[2]=mkent(h2, FH, Wv,    FH, 0, v,    bv,    NN, FH, FH, 0, 1, 0, nullptr);
        bt.e[3]=mkent(h2, FH, Wskip, FH, 0, attn, bskip, NN, FH, FH, 0, 1, 0, nullptr);
        bt.total=0; for(int i=0;i<bt.ng;i++) bt.total += bt.e[i].ntiles;
        k_bgemm<<<GB, T>>>(bt);
    }

    // ---- edge attention
    k_init_attn_state<<<(NN*NH+T-1)/T, T>>>(smax, denom, NN*NH);
    k_score <<<eWarps, T>>>(q, k, src, dst, score, smax, EE);
    k_expsum<<<(EE*NH+T-1)/T, T>>>(score, dst, smax, denom, EE);
    k_attn  <<<eWarps, T>>>(score, denom, v, src, dst, attn, EE);

    // Batch 4: gi gemm
    {
        Batch bt; bt.slot=3; bt.ng=1;
        bt.e[0]=mkent(attn, FH, W_ih, FH, 1, gi, b_ih, NN, G3, FH, 0, 0, 0, nullptr);
        bt.total=bt.e[0].ntiles;
        k_bgemm<<<GB, T>>>(bt);
    }

    // ---- GRU gates
    k_gru<<<((size_t)NN*FH+T-1)/T, T>>>(gi, gh, hprev, out);
}

// round 9
// speedup vs baseline: 1.3054x; 1.0029x over previous
#include <cuda_runtime.h>
#include <cuda_bf16.h>
#include <math.h>

#define NN   20000
#define EE   320000
#define FIN  128
#define FH   256
#define RR   4
#define NH   4
#define G3   (3*FH)

// ---------------- scratch pool (aliased lifetimes) --------------------------
#define OFF_AGG   ((size_t)0)
#define OFF_H1    (OFF_AGG  + (size_t)NN*RR*FH)
#define OFF_H2    (OFF_H1   + (size_t)NN*FH)
#define OFF_Q     (OFF_H2   + (size_t)NN*FH)
#define OFF_K     (OFF_Q    + (size_t)NN*FH)
#define OFF_V     (OFF_K    + (size_t)NN*FH)
#define OFF_ATTN  (OFF_V    + (size_t)NN*FH)
#define OFF_SCORE (OFF_ATTN + (size_t)NN*FH)
#define OFF_GHX   (OFF_SCORE+ (size_t)EE*NH)
#define POOL_SZ   (OFF_GHX  + (size_t)NN*G3)
#define OFF_GI    OFF_AGG                       // aliases agg (dead by GRU)

__device__ float g_pool[POOL_SZ];
__device__ float g_cnt[NN*RR];
__device__ int   g_smax[NN*NH];
__device__ float g_denom[NN*NH];
__device__ int   g_ticks[4];

// ---------------- helpers ---------------------------------------------------
__device__ __forceinline__ int f2oi(float f){ int i=__float_as_int(f); return i>=0 ? i : i^0x7fffffff; }
__device__ __forceinline__ float oi2f(int i){ return __int_as_float(i>=0 ? i : i^0x7fffffff); }
__device__ __forceinline__ float sigm(float x){ return 1.f/(1.f+expf(-x)); }
__device__ __forceinline__ float4 f4relu(float4 v){ return make_float4(fmaxf(v.x,0.f),fmaxf(v.y,0.f),fmaxf(v.z,0.f),fmaxf(v.w,0.f)); }
__device__ __forceinline__ float4 f4scale(float4 v, float s){ return make_float4(v.x*s,v.y*s,v.z*s,v.w*s); }

__global__ void k_zero_f(float* p, size_t n){
    for(size_t i=(size_t)blockIdx.x*blockDim.x+threadIdx.x; i<n; i+=(size_t)gridDim.x*blockDim.x) p[i]=0.f;
}
__global__ void k_tick0(){ if(threadIdx.x<4) g_ticks[threadIdx.x]=0; }
__global__ void k_seed_bias(float* C, const float* bias, int M, int N){
    size_t total=(size_t)M*N;
    for(size_t i=(size_t)blockIdx.x*blockDim.x+threadIdx.x; i<total; i+=(size_t)gridDim.x*blockDim.x)
        C[i]=bias[i%(size_t)N];
}
__global__ void k_init_attn_state(int* smax, float* denom, int n){
    int v = f2oi(-3.402823466e38f);
    for(int i=blockIdx.x*blockDim.x+threadIdx.x; i<n; i+=gridDim.x*blockDim.x){ smax[i]=v; denom[i]=0.f; }
}

// ---------------- edge kernels ----------------------------------------------
__global__ void k_count(const int* __restrict__ dst, const int* __restrict__ et, float* cnt, int E){
    for(int e=blockIdx.x*blockDim.x+threadIdx.x; e<E; e+=gridDim.x*blockDim.x)
        atomicAdd(&cnt[dst[e]*RR + et[e]], 1.f);
}

__global__ void k_scatter(const float* __restrict__ x, const int* __restrict__ src,
                          const int* __restrict__ dst, const int* __restrict__ et,
                          float* __restrict__ agg, int E, int F, int relu){
    int gtid = blockIdx.x*blockDim.x + threadIdx.x;
    int warp = gtid>>5, lane = gtid&31;
    int nw = (gridDim.x*blockDim.x)>>5;
    int F4 = F>>2;
    for(int e=warp; e<E; e+=nw){
        int s=src[e], d=dst[e], r=et[e];
        const float4* xs = (const float4*)(x + (size_t)s*F);
        float* ag = agg + ((size_t)d*RR + r)*F;
        for(int i=lane;i<F4;i+=32){
            float4 v = xs[i];
            if(relu) v = f4relu(v);
            atomicAdd(ag+4*i+0, v.x);
            atomicAdd(ag+4*i+1, v.y);
            atomicAdd(ag+4*i+2, v.z);
            atomicAdd(ag+4*i+3, v.w);
        }
    }
}

__global__ void k_score(const float* __restrict__ q, const float* __restrict__ kk,
                        const int* __restrict__ src, const int* __restrict__ dst,
                        float* __restrict__ score, int* __restrict__ smax, int E){
    int gtid = blockIdx.x*blockDim.x + threadIdx.x;
    int warp = gtid>>5, lane = gtid&31;
    int nw = (gridDim.x*blockDim.x)>>5;
    for(int e=warp; e<E; e+=nw){
        int s=src[e], d=dst[e];
        const float4* qd = (const float4*)(q  + (size_t)d*FH);
        const float4* ks = (const float4*)(kk + (size_t)s*FH);
        float4 a0=qd[lane],      b0=ks[lane];
        float4 a1=qd[lane+32],   b1=ks[lane+32];
        float p0 = a0.x*b0.x + a0.y*b0.y + a0.z*b0.z + a0.w*b0.w;
        float p1 = a1.x*b1.x + a1.y*b1.y + a1.z*b1.z + a1.w*b1.w;
        #pragma unroll
        for(int o=8;o>=1;o>>=1){
            p0 += __shfl_xor_sync(0xffffffffu, p0, o);
            p1 += __shfl_xor_sync(0xffffffffu, p1, o);
        }
        if((lane&15)==0){
            int h = lane>>4;
            float s0 = p0*0.125f, s1 = p1*0.125f;
            score[(size_t)e*NH + h]     = s0;
            score[(size_t)e*NH + h + 2] = s1;
            atomicMax(&smax[d*NH + h],     f2oi(s0));
            atomicMax(&smax[d*NH + h + 2], f2oi(s1));
        }
    }
}

__global__ void k_expsum(float* __restrict__ score, const int* __restrict__ dst,
                         const int* __restrict__ smax, float* __restrict__ denom, int E){
    int total = E*NH;
    for(int i=blockIdx.x*blockDim.x+threadIdx.x; i<total; i+=gridDim.x*blockDim.x){
        int e = i>>2, h = i&3;
        int d = dst[e];
        float m = oi2f(smax[d*NH + h]);
        float ex = expf(score[i]-m);
        score[i] = ex;
        atomicAdd(&denom[d*NH + h], ex);
    }
}

__global__ void k_attn(const float* __restrict__ score, const float* __restrict__ denom,
                       const float* __restrict__ v, const int* __restrict__ src,
                       const int* __restrict__ dst, float* __restrict__ out, int E){
    int gtid = blockIdx.x*blockDim.x + threadIdx.x;
    int warp = gtid>>5, lane = gtid&31;
    int nw = (gridDim.x*blockDim.x)>>5;
    for(int e=warp; e<E; e+=nw){
        int s=src[e], d=dst[e];
        int h0 = lane>>4;
        float a0 = score[(size_t)e*NH + h0]     / fmaxf(denom[d*NH + h0],     1e-16f);
        float a1 = score[(size_t)e*NH + h0 + 2] / fmaxf(denom[d*NH + h0 + 2], 1e-16f);
        const float4* vs = (const float4*)(v + (size_t)s*FH);
        float* od = out + (size_t)d*FH;
        float4 v0 = vs[lane];
        atomicAdd(od+4*lane+0,   a0*v0.x);
        atomicAdd(od+4*lane+1,   a0*v0.y);
        atomicAdd(od+4*lane+2,   a0*v0.z);
        atomicAdd(od+4*lane+3,   a0*v0.w);
        float4 v1 = vs[lane+32];
        atomicAdd(od+4*(lane+32)+0, a1*v1.x);
        atomicAdd(od+4*(lane+32)+1, a1*v1.y);
        atomicAdd(od+4*(lane+32)+2, a1*v1.z);
        atomicAdd(od+4*(lane+32)+3, a1*v1.w);
    }
}

__global__ void k_gru(const float* __restrict__ gi, const float* __restrict__ gh,
                      const float* __restrict__ hprev, float* __restrict__ out){
    size_t total = (size_t)NN*FH;
    for(size_t i=(size_t)blockIdx.x*blockDim.x+threadIdx.x; i<total; i+=(size_t)gridDim.x*blockDim.x){
        size_t n = i/FH; int j = (int)(i%FH);
        const float* gin = gi + n*G3;
        const float* ghn = gh + n*G3;
        float r = sigm(gin[j]       + ghn[j]);
        float z = sigm(gin[FH+j]    + ghn[FH+j]);
        float nw = tanhf(gin[2*FH+j] + r*ghn[2*FH+j]);
        out[i] = (1.f - z)*nw + z*hprev[i];
    }
}

// ---------------- batched persistent SGEMM ----------------------------------
// Tiles: 128x128, 256 threads, 8x8/thread, BK=16 double-buffered, FFMA2.
// Entry modes: mode 0=plain A, 1=relu(A), 2=A scaled by 1/max(cnt[row*RR+rr],1).
// Epilogue: atomic_ep ? atomicAdd into C (pre-seeded) : store C = acc + bias.
struct Entry {
    const float* A; const float* B; const float* bias; const float* cnt;
    float* C;
    int M, N, K, lda, ldb;
    int transB, atomic_ep, mode, rr;
    int tiles_n, ntiles;
};
struct Batch { int ng; int total; int slot; Entry e[6]; };

__global__ __launch_bounds__(256, 2)
void k_bgemm(Batch bt)
{
    __shared__ float As[2][16][128];
    __shared__ float Bs[2][16][128];
    __shared__ int s_t;
    const int tid = threadIdx.x;
    const int tr = tid>>4, tc = tid&15;
    const int la_m = tid>>1, la_k = (tid&1)*8;
    const int lb_k = tid>>5, lb_n = (tid&31)*4;

    for(;;){
        if(tid==0) s_t = atomicAdd(&g_ticks[bt.slot], 1);
        __syncthreads();
        int t = s_t;
        if(t >= bt.total) return;

        int g=0, base=0;
        while(t >= base + bt.e[g].ntiles){ base += bt.e[g].ntiles; g++; }
        const Entry E = bt.e[g];
        int lt = t - base;
        int tm = lt / E.tiles_n, tn = lt - tm*E.tiles_n;
        int m0 = tm*128, n0 = tn*128;

        unsigned long long acc2[8][4];
        #pragma unroll
        for(int i=0;i<8;i++)
            #pragma unroll
            for(int j=0;j<4;j++) acc2[i][j]=0ull;

        const bool a_ok = (m0+la_m < E.M);
        const float* Arow   = E.A + (size_t)(m0+la_m)*E.lda + la_k;
        const float* Brow_t = E.B + (size_t)(n0+la_m)*E.ldb + la_k;
        float ascale = 1.f;
        if(E.mode==2 && a_ok) ascale = 1.f/fmaxf(E.cnt[(m0+la_m)*RR + E.rr], 1.f);

        float4 ra0, ra1, rb0, rb1;
        #define LOAD_TILE(k0)                                                          \
            do{                                                                        \
                if(a_ok){ ra0 = *(const float4*)(Arow + (k0));                         \
                          ra1 = *(const float4*)(Arow + (k0) + 4);                     \
                          if(E.mode==1){ ra0=f4relu(ra0); ra1=f4relu(ra1); }           \
                          else if(E.mode==2){ ra0=f4scale(ra0,ascale);                 \
                                              ra1=f4scale(ra1,ascale); } }            \
                else    { ra0 = make_float4(0,0,0,0); ra1 = ra0; }                     \
                if(E.transB){                                                          \
                    rb0 = *(const float4*)(Brow_t + (k0));                             \
                    rb1 = *(const float4*)(Brow_t + (k0) + 4);                         \
                } else {                                                               \
                    rb0 = *(const float4*)(E.B + (size_t)((k0)+lb_k  )*E.ldb + n0+lb_n); \
                    rb1 = *(const float4*)(E.B + (size_t)((k0)+lb_k+8)*E.ldb + n0+lb_n); \
                }                                                                      \
            }while(0)

        #define STORE_TILE(buf)                                                        \
            do{                                                                        \
                As[buf][la_k+0][la_m]=ra0.x; As[buf][la_k+1][la_m]=ra0.y;              \
                As[buf][la_k+2][la_m]=ra0.z; As[buf][la_k+3][la_m]=ra0.w;              \
                As[buf][la_k+4][la_m]=ra1.x; As[buf][la_k+5][la_m]=ra1.y;              \
                As[buf][la_k+6][la_m]=ra1.z; As[buf][la_k+7][la_m]=ra1.w;              \
                if(E.transB){                                                          \
                    Bs[buf][la_k+0][la_m]=rb0.x; Bs[buf][la_k+1][la_m]=rb0.y;          \
                    Bs[buf][la_k+2][la_m]=rb0.z; Bs[buf][la_k+3][la_m]=rb0.w;          \
                    Bs[buf][la_k+4][la_m]=rb1.x; Bs[buf][la_k+5][la_m]=rb1.y;          \
                    Bs[buf][la_k+6][la_m]=rb1.z; Bs[buf][la_k+7][la_m]=rb1.w;          \
                } else {                                                               \
                    *(float4*)&Bs[buf][lb_k  ][lb_n] = rb0;                            \
                    *(float4*)&Bs[buf][lb_k+8][lb_n] = rb1;                            \
                }                                                                      \
            }while(0)

        #define COMPUTE(buf)                                                           \
            do{                                                                        \
                _Pragma("unroll")                                                      \
                for(int kkk=0;kkk<16;kkk++){                                           \
                    float a[8];                                                        \
                    *(float4*)&a[0] = *(const float4*)&As[buf][kkk][tr*8];             \
                    *(float4*)&a[4] = *(const float4*)&As[buf][kkk][tr*8+4];           \
                    unsigned long long b2[4];                                          \
                    const unsigned long long* bp =                                     \
                        (const unsigned long long*)&Bs[buf][kkk][tc*8];                \
                    b2[0]=bp[0]; b2[1]=bp[1]; b2[2]=bp[2]; b2[3]=bp[3];                \
                    _Pragma("unroll")                                                  \
                    for(int i=0;i<8;i++){                                              \
                        unsigned long long a2;                                         \
                        asm("mov.b64 %0, {%1, %1};" : "=l"(a2) : "f"(a[i]));           \
                        _Pragma("unroll")                                              \
                        for(int j=0;j<4;j++)                                           \
                            asm("fma.rn.f32x2 %0, %1, %2, %0;"                         \
                                : "+l"(acc2[i][j]) : "l"(a2), "l"(b2[j]));             \
                    }                                                                  \
                }                                                                      \
            }while(0)

        LOAD_TILE(0);
        STORE_TILE(0);
        __syncthreads();
        int buf = 0;
        for(int k0=16; k0<E.K; k0+=16){
            LOAD_TILE(k0);
            COMPUTE(buf);
            STORE_TILE(buf^1);
            __syncthreads();
            buf ^= 1;
        }
        COMPUTE(buf);
        #undef LOAD_TILE
        #undef STORE_TILE
        #undef COMPUTE

        #pragma unroll
        for(int i=0;i<8;i++){
            int row = m0 + tr*8 + i;
            if(row >= E.M) break;
            float* crow = E.C + (size_t)row*E.N + n0;
            #pragma unroll
            for(int j=0;j<4;j++){
                float lo, hi;
                asm("mov.b64 {%0, %1}, %2;" : "=f"(lo), "=f"(hi) : "l"(acc2[i][j]));
                int c0 = tc*8 + 2*j;
                if(E.atomic_ep){
                    atomicAdd(crow+c0,   lo);
                    atomicAdd(crow+c0+1, hi);
                } else {
                    crow[c0]   = lo + E.bias[n0+c0];
                    crow[c0+1] = hi + E.bias[n0+c0+1];
                }
            }
        }
        __syncthreads();   // protect smem + s_t before next ticket
    }
}

// ---------------- host ------------------------------------------------------
static Entry mkent(const float* A, int lda, const float* B, int ldb, int transB,
                   float* C, const float* bias, int M, int N, int K,
                   int atomic_ep, int mode, int rr, const float* cnt){
    Entry e;
    e.A=A; e.B=B; e.bias=bias; e.cnt=cnt; e.C=C;
    e.M=M; e.N=N; e.K=K; e.lda=lda; e.ldb=ldb;
    e.transB=transB; e.atomic_ep=atomic_ep; e.mode=mode; e.rr=rr;
    e.tiles_n = N/128;
    e.ntiles  = ((M+127)/128) * e.tiles_n;
    return e;
}

extern "C" void kernel_launch(void* const* d_in, const int* in_sizes, int n_in,
                              void* d_out, int out_size)
{
    const float* x      = (const float*)d_in[0];
    const int*   eidx   = (const int*)  d_in[1];
    const int*   src    = eidx;
    const int*   dst    = eidx + EE;
    const int*   et     = (const int*)  d_in[2];
    const float* hprev  = (const float*)d_in[3];
    const float* W1     = (const float*)d_in[4];
    const float* root1  = (const float*)d_in[5];
    const float* b1     = (const float*)d_in[6];
    const float* W2     = (const float*)d_in[7];
    const float* root2  = (const float*)d_in[8];
    const float* b2     = (const float*)d_in[9];
    const float* Wq     = (const float*)d_in[10];
    const float* bq     = (const float*)d_in[11];
    const float* Wk     = (const float*)d_in[12];
    const float* bk     = (const float*)d_in[13];
    const float* Wv     = (const float*)d_in[14];
    const float* bv     = (const float*)d_in[15];
    const float* Wskip  = (const float*)d_in[16];
    const float* bskip  = (const float*)d_in[17];
    const float* W_ih   = (const float*)d_in[18];
    const float* b_ih   = (const float*)d_in[19];
    const float* W_hh   = (const float*)d_in[20];
    const float* b_hh   = (const float*)d_in[21];
    float* out = (float*)d_out;

    static float* pool = nullptr;
    static float* cnt; static int* smax; static float* denom;
    if(!pool){
        void* p;
        cudaGetSymbolAddress(&p, g_pool);  pool  = (float*)p;
        cudaGetSymbolAddress(&p, g_cnt);   cnt   = (float*)p;
        cudaGetSymbolAddress(&p, g_smax);  smax  = (int*)p;
        cudaGetSymbolAddress(&p, g_denom); denom = (float*)p;
    }
    float* agg   = pool + OFF_AGG;
    float* h1    = pool + OFF_H1;
    float* h2    = pool + OFF_H2;
    float* q     = pool + OFF_Q;
    float* k     = pool + OFF_K;
    float* v     = pool + OFF_V;
    float* attn  = pool + OFF_ATTN;
    float* score = pool + OFF_SCORE;
    float* gh    = pool + OFF_GHX;
    float* gi    = pool + OFF_GI;

    const int T = 256;
    const int GB = 304;                 // persistent gemm blocks (2 x 152 SMs)
    int eWarps = (EE*32 + T-1)/T;

    k_tick0<<<1,32>>>();

    // ---- counts
    k_zero_f<<<(NN*RR+T-1)/T, T>>>(cnt, (size_t)NN*RR);
    k_count <<<(EE+T-1)/T,    T>>>(dst, et, cnt, EE);

    // ---- RGCN layer 1 scatter (no norm kernel; folded into gemm A-load)
    k_zero_f<<<((size_t)NN*RR*FIN+T-1)/T, T>>>(agg, (size_t)NN*RR*FIN);
    k_scatter<<<eWarps, T>>>(x, src, dst, et, agg, EE, FIN, 0);
    k_seed_bias<<<1024, T>>>(h1, b1, NN, FH);

    // Batch 1: RGCN1 (root + 4 relation K-chunks, atomic) + gh gemm (independent)
    {
        Batch bt; bt.slot=0; bt.ng=6;
        bt.e[0]=mkent(x,   FIN,  root1,          FH, 0, h1, nullptr, NN, FH, FIN, 1, 0, 0, nullptr);
        for(int r=0;r<RR;r++)
            bt.e[1+r]=mkent(agg + r*FIN, RR*FIN, W1 + (size_t)r*FIN*FH, FH, 0,
                            h1, nullptr, NN, FH, FIN, 1, 2, r, cnt);
        bt.e[5]=mkent(hprev, FH, W_hh, FH, 1, gh, b_hh, NN, G3, FH, 0, 0, 0, nullptr);
        bt.total=0; for(int i=0;i<bt.ng;i++) bt.total += bt.e[i].ntiles;
        k_bgemm<<<GB, T>>>(bt);
    }

    // ---- RGCN layer 2 scatter (reads relu(h1))
    k_zero_f<<<((size_t)NN*RR*FH+T-1)/T, T>>>(agg, (size_t)NN*RR*FH);
    k_scatter<<<eWarps, T>>>(h1, src, dst, et, agg, EE, FH, 1);
    k_seed_bias<<<1024, T>>>(h2, b2, NN, FH);

    // Batch 2: RGCN2 (root reads relu(h1); 4 relation chunks, all atomic)
    {
        Batch bt; bt.slot=1; bt.ng=5;
        bt.e[0]=mkent(h1, FH, root2, FH, 0, h2, nullptr, NN, FH, FH, 1, 1, 0, nullptr);
        for(int r=0;r<RR;r++)
            bt.e[1+r]=mkent(agg + r*FH, RR*FH, W2 + (size_t)r*FH*FH, FH, 0,
                            h2, nullptr, NN, FH, FH, 1, 2, r, cnt);
        bt.total=0; for(int i=0;i<bt.ng;i++) bt.total += bt.e[i].ntiles;
        k_bgemm<<<GB, T>>>(bt);
    }

    // Batch 3: q/k/v/skip (A = relu(h2))
    {
        Batch bt; bt.slot=2; bt.ng=4;
        bt.e[0]=mkent(h2, FH, Wq,    FH, 0, q,    bq,    NN, FH, FH, 0, 1, 0, nullptr);
        bt.e[1]=mkent(h2, FH, Wk,    FH, 0, k,    bk,    NN, FH, FH, 0, 1, 0, nullptr);
        bt.e[2]=mkent(h2, FH, Wv,    FH, 0, v,    bv,    NN, FH, FH, 0, 1, 0, nullptr);
        bt.e[3]=mkent(h2, FH, Wskip, FH, 0, attn, bskip, NN, FH, FH, 0, 1, 0, nullptr);
        bt.total=0; for(int i=0;i<bt.ng;i++) bt.total += bt.e[i].ntiles;
        k_bgemm<<<GB, T>>>(bt);
    }

    // ---- edge attention
    k_init_attn_state<<<(NN*NH+T-1)/T, T>>>(smax, denom, NN*NH);
    k_score <<<eWarps, T>>>(q, k, src, dst, score, smax, EE);
    k_expsum<<<(EE*NH+T-1)/T, T>>>(score, dst, smax, denom, EE);
    k_attn  <<<eWarps, T>>>(score, denom, v, src, dst, attn, EE);

    // Batch 4: gi gemm
    {
        Batch bt; bt.slot=3; bt.ng=1;
        bt.e[0]=mkent(attn, FH, W_ih, FH, 1, gi, b_ih, NN, G3, FH, 0, 0, 0, nullptr);
        bt.total=bt.e[0].ntiles;
        k_bgemm<<<GB, T>>>(bt);
    }

    // ---- GRU gates
    k_gru<<<((size_t)NN*FH+T-1)/T, T>>>(gi, gh, hprev, out);
}

// round 11
// speedup vs baseline: 1.8511x; 1.4181x over previous
#include <cuda_runtime.h>
#include <cuda_bf16.h>
#include <mma.h>
#include <math.h>
#include <stdint.h>
using namespace nvcuda;

#define NN 20000
#define EE 320000
#define FIN 128
#define FH 256
#define RR 4
#define NH 4
#define G3 (3*FH)

#define OFF_AGG   ((size_t)0)
#define OFF_H1    (OFF_AGG + (size_t)NN*RR*FH)
#define OFF_H2    (OFF_H1  + (size_t)NN*FH)
#define OFF_Q     (OFF_H2  + (size_t)NN*FH)
#define OFF_K     (OFF_Q   + (size_t)NN*FH)
#define OFF_V     (OFF_K   + (size_t)NN*FH)
#define OFF_ATTN  (OFF_V   + (size_t)NN*FH)
#define OFF_SCORE (OFF_ATTN+ (size_t)NN*FH)
#define OFF_GHX   (OFF_SCORE+(size_t)EE*NH)
#define POOL_SZ   (OFF_GHX + (size_t)NN*G3)
#define OFF_GI    OFF_AGG

__device__ float g_pool[POOL_SZ];
__device__ float g_cnt[NN*RR];
__device__ int   g_smax[NN*NH];
__device__ float g_denom[NN*NH];
__device__ int   g_ticks[4];

// bf16 hi/lo weights, row-major [K][N]
#define WTOT 1146880
__device__ __align__(16) __nv_bfloat16 g_wh[WTOT];
__device__ __align__(16) __nv_bfloat16 g_wl[WTOT];
#define WO_W1 0
#define WO_W2 131072
#define WO_R1 393216
#define WO_R2 425984
#define WO_Q  491520
#define WO_KW 557056
#define WO_VW 622592
#define WO_SK 688128
#define WO_IH 753664
#define WO_HH 950272

__device__ __forceinline__ int f2oi(float f){ int i=__float_as_int(f); return i>=0?i:i^0x7fffffff; }
__device__ __forceinline__ float oi2f(int i){ return __int_as_float(i>=0?i:i^0x7fffffff); }
__device__ __forceinline__ float sigm(float x){ return 1.f/(1.f+expf(-x)); }
__device__ __forceinline__ float4 f4relu(float4 v){ return make_float4(fmaxf(v.x,0.f),fmaxf(v.y,0.f),fmaxf(v.z,0.f),fmaxf(v.w,0.f)); }
__device__ __forceinline__ float4 f4s(float4 v,float s){ return make_float4(v.x*s,v.y*s,v.z*s,v.w*s); }

__global__ void k_zero_f(float* p, size_t n){ for(size_t i=(size_t)blockIdx.x*blockDim.x+threadIdx.x;i<n;i+=(size_t)gridDim.x*blockDim.x) p[i]=0.f; }
__global__ void k_tick0(){ if(threadIdx.x<4) g_ticks[threadIdx.x]=0; }
__global__ void k_seed_bias(float* C, const float* bias, int M, int N){
    size_t tot=(size_t)M*N;
    for(size_t i=(size_t)blockIdx.x*blockDim.x+threadIdx.x;i<tot;i+=(size_t)gridDim.x*blockDim.x) C[i]=bias[i%(size_t)N];
}
__global__ void k_init_attn(int* smax, float* denom, int n){
    int v=f2oi(-3.402823466e38f);
    for(int i=blockIdx.x*blockDim.x+threadIdx.x;i<n;i+=gridDim.x*blockDim.x){ smax[i]=v; denom[i]=0.f; }
}
__global__ void k_count(const int* __restrict__ dst, const int* __restrict__ et, float* cnt, int E){
    for(int e=blockIdx.x*blockDim.x+threadIdx.x;e<E;e+=gridDim.x*blockDim.x) atomicAdd(&cnt[dst[e]*RR+et[e]],1.f);
}
__global__ void k_scatter(const float* __restrict__ x, const int* __restrict__ src, const int* __restrict__ dst,
                          const int* __restrict__ et, float* __restrict__ agg, int E, int F, int relu){
    int g=blockIdx.x*blockDim.x+threadIdx.x, w=g>>5, l=g&31, nw=(gridDim.x*blockDim.x)>>5, F4=F>>2;
    for(int e=w;e<E;e+=nw){
        int s=src[e], d=dst[e], r=et[e];
        const float4* xs=(const float4*)(x+(size_t)s*F);
        float* ag=agg+((size_t)d*RR+r)*F;
        for(int i=l;i<F4;i+=32){
            float4 v=xs[i]; if(relu) v=f4relu(v);
            atomicAdd(ag+4*i,v.x); atomicAdd(ag+4*i+1,v.y); atomicAdd(ag+4*i+2,v.z); atomicAdd(ag+4*i+3,v.w);
        }
    }
}
__global__ void k_score(const float* __restrict__ q, const float* __restrict__ kk, const int* __restrict__ src,
                        const int* __restrict__ dst, float* __restrict__ score, int* __restrict__ smax, int E){
    int g=blockIdx.x*blockDim.x+threadIdx.x, w=g>>5, l=g&31, nw=(gridDim.x*blockDim.x)>>5;
    for(int e=w;e<E;e+=nw){
        int s=src[e], d=dst[e];
        const float4* qd=(const float4*)(q+(size_t)d*FH);
        const float4* ks=(const float4*)(kk+(size_t)s*FH);
        float4 a0=qd[l],b0=ks[l],a1=qd[l+32],b1=ks[l+32];
        float p0=a0.x*b0.x+a0.y*b0.y+a0.z*b0.z+a0.w*b0.w;
        float p1=a1.x*b1.x+a1.y*b1.y+a1.z*b1.z+a1.w*b1.w;
        #pragma unroll
        for(int o=8;o>=1;o>>=1){ p0+=__shfl_xor_sync(~0u,p0,o); p1+=__shfl_xor_sync(~0u,p1,o); }
        if((l&15)==0){
            int h=l>>4; float s0=p0*0.125f,s1=p1*0.125f;
            score[(size_t)e*NH+h]=s0; score[(size_t)e*NH+h+2]=s1;
            atomicMax(&smax[d*NH+h],f2oi(s0)); atomicMax(&smax[d*NH+h+2],f2oi(s1));
        }
    }
}
__global__ void k_expsum(float* __restrict__ score, const int* __restrict__ dst, const int* __restrict__ smax,
                         float* __restrict__ denom, int E){
    int tot=E*NH;
    for(int i=blockIdx.x*blockDim.x+threadIdx.x;i<tot;i+=gridDim.x*blockDim.x){
        int e=i>>2,h=i&3,d=dst[e];
        float ex=expf(score[i]-oi2f(smax[d*NH+h]));
        score[i]=ex; atomicAdd(&denom[d*NH+h],ex);
    }
}
__global__ void k_attn(const float* __restrict__ score, const float* __restrict__ denom, const float* __restrict__ v,
                       const int* __restrict__ src, const int* __restrict__ dst, float* __restrict__ out, int E){
    int g=blockIdx.x*blockDim.x+threadIdx.x, w=g>>5, l=g&31, nw=(gridDim.x*blockDim.x)>>5;
    for(int e=w;e<E;e+=nw){
        int s=src[e], d=dst[e], h0=l>>4;
        float a0=score[(size_t)e*NH+h0]/fmaxf(denom[d*NH+h0],1e-16f);
        float a1=score[(size_t)e*NH+h0+2]/fmaxf(denom[d*NH+h0+2],1e-16f);
        const float4* vs=(const float4*)(v+(size_t)s*FH);
        float* od=out+(size_t)d*FH;
        float4 v0=vs[l];
        atomicAdd(od+4*l,a0*v0.x); atomicAdd(od+4*l+1,a0*v0.y); atomicAdd(od+4*l+2,a0*v0.z); atomicAdd(od+4*l+3,a0*v0.w);
        float4 v1=vs[l+32];
        atomicAdd(od+4*(l+32),a1*v1.x); atomicAdd(od+4*(l+32)+1,a1*v1.y); atomicAdd(od+4*(l+32)+2,a1*v1.z); atomicAdd(od+4*(l+32)+3,a1*v1.w);
    }
}
__global__ void k_gru(const float* __restrict__ gi, const float* __restrict__ gh, const float* __restrict__ hp, float* __restrict__ out){
    size_t tot=(size_t)NN*FH;
    for(size_t i=(size_t)blockIdx.x*blockDim.x+threadIdx.x;i<tot;i+=(size_t)gridDim.x*blockDim.x){
        size_t n=i/FH; int j=(int)(i%FH);
        const float* a=gi+n*G3; const float* b=gh+n*G3;
        float r=sigm(a[j]+b[j]), z=sigm(a[FH+j]+b[FH+j]);
        float nw=tanhf(a[2*FH+j]+r*b[2*FH+j]);
        out[i]=(1.f-z)*nw+z*hp[i];
    }
}

// fp32 weights -> bf16 hi/lo row-major [K][N]; trans: input is [N][K]
struct WEnt{ const float* W; __nv_bfloat16* dh; __nv_bfloat16* dl; int K,N,trans; };
struct WTab{ int tot; WEnt e[10]; int off[11]; };
__global__ void k_wconv(WTab t){
    int stride=gridDim.x*blockDim.x;
    for(int i=blockIdx.x*blockDim.x+threadIdx.x;i<t.tot;i+=stride){
        int g=0; while(i>=t.off[g+1]) g++;
        WEnt E=t.e[g]; int li=i-t.off[g];
        float w;
        if(!E.trans) w = E.W[li];
        else { int k=li/E.N, n=li-k*E.N; w = E.W[(size_t)n*E.K+k]; }
        __nv_bfloat16 hi=__float2bfloat16_rn(w);
        E.dh[li]=hi;
        E.dl[li]=__float2bfloat16_rn(w-__bfloat162float(hi));
    }
}

// ---------- persistent batched WMMA bf16 GEMM (3-term split) ----------------
// Tile 128x128, 256 thr (8 warps, 4x2, each 32x64), BK=16, double-buffered.
struct Entry{
    const float* A; const __nv_bfloat16* Bh; const __nv_bfloat16* Bl;
    const float* bias; const float* cnt; float* C;
    int M,N,K,lda,ldb, atomic_ep, mode, rr, tiles_n, ntiles;
};
struct Batch{ int ng,total,slot; Entry e[6]; };

#define ALD 24
#define BLD 144
#define A_ELEMS (2*128*ALD)
#define B_ELEMS (2*16*BLD)
#define SMEM_DYN 65536

__global__ __launch_bounds__(256,2) void k_bgemm(Batch bt){
    extern __shared__ char sm[];
    __nv_bfloat16* Ah = (__nv_bfloat16*)sm;
    __nv_bfloat16* Al = Ah + A_ELEMS;
    __nv_bfloat16* Bhs = Al + A_ELEMS;
    __nv_bfloat16* Bls = Bhs + B_ELEMS;
    float* eps = (float*)sm;
    __shared__ int s_t;
    const int tid=threadIdx.x, wid=tid>>5, lid=tid&31;
    const int wr=wid>>1, wc=wid&1;
    const int arow=tid>>1, ak=(tid&1)*8;
    const int brow=tid>>4, bc=(tid&15)*8;

    for(;;){
        if(tid==0) s_t=atomicAdd(&g_ticks[bt.slot],1);
        __syncthreads();
        int t=s_t; if(t>=bt.total) return;
        int g=0,base=0;
        while(t>=base+bt.e[g].ntiles){ base+=bt.e[g].ntiles; g++; }
        const Entry E=bt.e[g];
        int lt=t-base, tm=lt/E.tiles_n, tn=lt-tm*E.tiles_n, m0=tm*128, n0=tn*128;

        wmma::fragment<wmma::accumulator,16,16,16,float> acc[2][4];
        #pragma unroll
        for(int i=0;i<2;i++)
            #pragma unroll
            for(int j=0;j<4;j++) wmma::fill_fragment(acc[i][j],0.f);

        const bool aok=(m0+arow<E.M);
        const float* abase = E.A + (size_t)(m0+arow)*E.lda + ak;
        float asc=1.f;
        if(E.mode==2) asc = aok ? 1.f/fmaxf(E.cnt[(m0+arow)*RR+E.rr],1.f) : 0.f;
        const __nv_bfloat16* bhg = E.Bh + (size_t)brow*E.ldb + n0 + bc;
        const __nv_bfloat16* blg = E.Bl + (size_t)brow*E.ldb + n0 + bc;

        float4 fa0,fa1; uint4 rbh,rbl;
        #define LOADT(k0) do{                                                   \
            if(aok){ fa0=*(const float4*)(abase+(k0)); fa1=*(const float4*)(abase+(k0)+4); \
                     if(E.mode==1){ fa0=f4relu(fa0); fa1=f4relu(fa1); }          \
                     else if(E.mode==2){ fa0=f4s(fa0,asc); fa1=f4s(fa1,asc); } } \
            else { fa0=make_float4(0,0,0,0); fa1=fa0; }                          \
            rbh=*(const uint4*)(bhg+(size_t)(k0)*E.ldb);                         \
            rbl=*(const uint4*)(blg+(size_t)(k0)*E.ldb);                         \
        }while(0)

        #define STORET(b) do{                                                    \
            __nv_bfloat16* ph=Ah+(b)*128*ALD+arow*ALD+ak;                        \
            __nv_bfloat16* pl=Al+(b)*128*ALD+arow*ALD+ak;                        \
            float fv[8]={fa0.x,fa0.y,fa0.z,fa0.w,fa1.x,fa1.y,fa1.z,fa1.w};       \
            _Pragma("unroll")                                                    \
            for(int u=0;u<8;u++){                                                \
                __nv_bfloat16 h=__float2bfloat16_rn(fv[u]);                      \
                ph[u]=h; pl[u]=__float2bfloat16_rn(fv[u]-__bfloat162float(h));   \
            }                                                                    \
            *(uint4*)(Bhs+(b)*16*BLD+brow*BLD+bc)=rbh;                           \
            *(uint4*)(Bls+(b)*16*BLD+brow*BLD+bc)=rbl;                           \
        }while(0)

        #define COMPUTE(b) do{                                                   \
            const __nv_bfloat16* pa_h=Ah+(b)*128*ALD+(wr*32)*ALD;                \
            const __nv_bfloat16* pa_l=Al+(b)*128*ALD+(wr*32)*ALD;                \
            const __nv_bfloat16* pb_h=Bhs+(b)*16*BLD+wc*64;                      \
            const __nv_bfloat16* pb_l=Bls+(b)*16*BLD+wc*64;                      \
            wmma::fragment<wmma::matrix_a,16,16,16,__nv_bfloat16,wmma::row_major> ah[2],al2[2]; \
            wmma::fragment<wmma::matrix_b,16,16,16,__nv_bfloat16,wmma::row_major> bh[4],bl2[4]; \
            _Pragma("unroll")                                                    \
            for(int i=0;i<2;i++){ wmma::load_matrix_sync(ah[i],pa_h+i*16*ALD,ALD); \
                                  wmma::load_matrix_sync(al2[i],pa_l+i*16*ALD,ALD); } \
            _Pragma("unroll")                                                    \
            for(int j=0;j<4;j++){ wmma::load_matrix_sync(bh[j],pb_h+j*16,BLD);   \
                                  wmma::load_matrix_sync(bl2[j],pb_l+j*16,BLD); } \
            _Pragma("unroll")                                                    \
            for(int i=0;i<2;i++)                                                 \
                _Pragma("unroll")                                                \
                for(int j=0;j<4;j++){                                            \
                    wmma::mma_sync(acc[i][j],ah[i],bh[j],acc[i][j]);             \
                    wmma::mma_sync(acc[i][j],al2[i],bh[j],acc[i][j]);            \
                    wmma::mma_sync(acc[i][j],ah[i],bl2[j],acc[i][j]);            \
                }                                                                \
        }while(0)

        LOADT(0); STORET(0);
        __syncthreads();
        int buf=0;
        for(int k0=16;k0<E.K;k0+=16){
            LOADT(k0);
            COMPUTE(buf);
            STORET(buf^1);
            __syncthreads();
            buf^=1;
        }
        COMPUTE(buf);
        __syncthreads();   // all warps done with A/B smem; eps may alias it
        #undef LOADT
        #undef STORET
        #undef COMPUTE

        // epilogue: per-warp 32x64 region
        float* ep = eps + wid*2048;
        #pragma unroll
        for(int i=0;i<2;i++)
            #pragma unroll
            for(int j=0;j<4;j++)
                wmma::store_matrix_sync(ep + i*16*64 + j*16, acc[i][j], 64, wmma::mem_row_major);
        __syncwarp();
        int c0 = n0 + wc*64 + lid*2;
        for(int r2=0;r2<32;r2++){
            int row = m0 + wr*32 + r2;
            if(row >= E.M) break;
            float v0=ep[r2*64+lid*2], v1=ep[r2*64+lid*2+1];
            float* crow = E.C + (size_t)row*E.N + c0;
            if(E.atomic_ep){ atomicAdd(crow,v0); atomicAdd(crow+1,v1); }
            else { crow[0]=v0+E.bias[c0]; crow[1]=v1+E.bias[c0+1]; }
        }
        __syncthreads();
    }
}

static Entry mkent(const float* A,int lda,const __nv_bfloat16* bh,const __nv_bfloat16* bl,int ldb,
                   float* C,const float* bias,int M,int N,int K,int atomic_ep,int mode,int rr,const float* cnt){
    Entry e; e.A=A; e.Bh=bh; e.Bl=bl; e.bias=bias; e.cnt=cnt; e.C=C;
    e.M=M; e.N=N; e.K=K; e.lda=lda; e.ldb=ldb;
    e.atomic_ep=atomic_ep; e.mode=mode; e.rr=rr;
    e.tiles_n=N/128; e.ntiles=((M+127)/128)*e.tiles_n;
    return e;
}

extern "C" void kernel_launch(void* const* d_in, const int* in_sizes, int n_in, void* d_out, int out_size){
    const float* x=(const float*)d_in[0];
    const int* eidx=(const int*)d_in[1];
    const int* src=eidx; const int* dst=eidx+EE;
    const int* et=(const int*)d_in[2];
    const float* hprev=(const float*)d_in[3];
    const float* W1=(const float*)d_in[4];   const float* root1=(const float*)d_in[5];  const float* b1=(const float*)d_in[6];
    const float* W2=(const float*)d_in[7];   const float* root2=(const float*)d_in[8];  const float* b2=(const float*)d_in[9];
    const float* Wq=(const float*)d_in[10];  const float* bq=(const float*)d_in[11];
    const float* Wk=(const float*)d_in[12];  const float* bk=(const float*)d_in[13];
    const float* Wv=(const float*)d_in[14];  const float* bv=(const float*)d_in[15];
    const float* Wskip=(const float*)d_in[16]; const float* bskip=(const float*)d_in[17];
    const float* W_ih=(const float*)d_in[18]; const float* b_ih=(const float*)d_in[19];
    const float* W_hh=(const float*)d_in[20]; const float* b_hh=(const float*)d_in[21];
    float* out=(float*)d_out;

    static float* pool=nullptr; static float* cnt; static int* smax; static float* denom;
    static __nv_bfloat16 *wh,*wl;
    if(!pool){
        void* p;
        cudaGetSymbolAddress(&p,g_pool); pool=(float*)p;
        cudaGetSymbolAddress(&p,g_cnt); cnt=(float*)p;
        cudaGetSymbolAddress(&p,g_smax); smax=(int*)p;
        cudaGetSymbolAddress(&p,g_denom); denom=(float*)p;
        cudaGetSymbolAddress(&p,g_wh); wh=(__nv_bfloat16*)p;
        cudaGetSymbolAddress(&p,g_wl); wl=(__nv_bfloat16*)p;
        cudaFuncSetAttribute(k_bgemm, cudaFuncAttributeMaxDynamicSharedMemorySize, SMEM_DYN);
    }
    float* agg=pool+OFF_AGG; float* h1=pool+OFF_H1; float* h2=pool+OFF_H2;
    float* q=pool+OFF_Q; float* k=pool+OFF_K; float* v=pool+OFF_V;
    float* attn=pool+OFF_ATTN; float* score=pool+OFF_SCORE;
    float* gh=pool+OFF_GHX; float* gi=pool+OFF_GI;

    const int T=256, GB=304;
    int eW=(EE*32+T-1)/T;

    k_tick0<<<1,32>>>();
    { // weight conversion
        WTab wt; int idx=0; int sz[10];
        auto add=[&](const float* W,int K,int N,int tr,int off){ wt.e[idx]=WEnt{W,wh+off,wl+off,K,N,tr}; sz[idx]=N*K; idx++; };
        add(W1,512,256,0,WO_W1);
        add(W2,1024,256,0,WO_W2);
        add(root1,128,256,0,WO_R1);
        add(root2,256,256,0,WO_R2);
        add(Wq,256,256,0,WO_Q); add(Wk,256,256,0,WO_KW); add(Wv,256,256,0,WO_VW); add(Wskip,256,256,0,WO_SK);
        add(W_ih,256,768,1,WO_IH); add(W_hh,256,768,1,WO_HH);
        wt.off[0]=0; for(int i=0;i<10;i++) wt.off[i+1]=wt.off[i]+sz[i];
        wt.tot=wt.off[10];
        k_wconv<<<2048,T>>>(wt);
    }
    k_zero_f<<<(NN*RR+T-1)/T,T>>>(cnt,(size_t)NN*RR);
    k_count<<<(EE+T-1)/T,T>>>(dst,et,cnt,EE);

    k_zero_f<<<((size_t)NN*RR*FIN+T-1)/T,T>>>(agg,(size_t)NN*RR*FIN);
    k_scatter<<<eW,T>>>(x,src,dst,et,agg,EE,FIN,0);
    k_seed_bias<<<1024,T>>>(h1,b1,NN,FH);
    { // batch 1: RGCN1 (root + 4 relations, atomic) + gh
        Batch bt; bt.slot=0; bt.ng=6;
        bt.e[0]=mkent(x,FIN, wh+WO_R1,wl+WO_R1,FH, h1,nullptr, NN,FH,FIN, 1,0,0,nullptr);
        for(int r=0;r<RR;r++)
            bt.e[1+r]=mkent(agg+r*FIN,RR*FIN, wh+WO_W1+r*FIN*FH,wl+WO_W1+r*FIN*FH,FH,
                            h1,nullptr, NN,FH,FIN, 1,2,r,cnt);
        bt.e[5]=mkent(hprev,FH, wh+WO_HH,wl+WO_HH,G3, gh,b_hh, NN,G3,FH, 0,0,0,nullptr);
        bt.total=0; for(int i=0;i<bt.ng;i++) bt.total+=bt.e[i].ntiles;
        k_bgemm<<<GB,T,SMEM_DYN>>>(bt);
    }
    k_zero_f<<<((size_t)NN*RR*FH+T-1)/T,T>>>(agg,(size_t)NN*RR*FH);
    k_scatter<<<eW,T>>>(h1,src,dst,et,agg,EE,FH,1);
    k_seed_bias<<<1024,T>>>(h2,b2,NN,FH);
    { // batch 2: RGCN2
        Batch bt; bt.slot=1; bt.ng=5;
        bt.e[0]=mkent(h1,FH, wh+WO_R2,wl+WO_R2,FH, h2,nullptr, NN,FH,FH, 1,1,0,nullptr);
        for(int r=0;r<RR;r++)
            bt.e[1+r]=mkent(agg+r*FH,RR*FH, wh+WO_W2+r*FH*FH,wl+WO_W2+r*FH*FH,FH,
                            h2,nullptr, NN,FH,FH, 1,2,r,cnt);
        bt.total=0; for(int i=0;i<bt.ng;i++) bt.total+=bt.e[i].ntiles;
        k_bgemm<<<GB,T,SMEM_DYN>>>(bt);
    }
    { // batch 3: q/k/v/skip
        Batch bt; bt.slot=2; bt.ng=4;
        bt.e[0]=mkent(h2,FH, wh+WO_Q, wl+WO_Q, FH, q,   bq,   NN,FH,FH, 0,1,0,nullptr);
        bt.e[1]=mkent(h2,FH, wh+WO_KW,wl+WO_KW,FH, k,   bk,   NN,FH,FH, 0,1,0,nullptr);
        bt.e[2]=mkent(h2,FH, wh+WO_VW,wl+WO_VW,FH, v,   bv,   NN,FH,FH, 0,1,0,nullptr);
        bt.e[3]=mkent(h2,FH, wh+WO_SK,wl+WO_SK,FH, attn,bskip,NN,FH,FH, 0,1,0,nullptr);
        bt.total=0; for(int i=0;i<bt.ng;i++) bt.total+=bt.e[i].ntiles;
        k_bgemm<<<GB,T,SMEM_DYN>>>(bt);
    }
    k_init_attn<<<(NN*NH+T-1)/T,T>>>(smax,denom,NN*NH);
    k_score<<<eW,T>>>(q,k,src,dst,score,smax,EE);
    k_expsum<<<(EE*NH+T-1)/T,T>>>(score,dst,smax,denom,EE);
    k_attn<<<eW,T>>>(score,denom,v,src,dst,attn,EE);
    { // batch 4: gi
        Batch bt; bt.slot=3; bt.ng=1;
        bt.e[0]=mkent(attn,FH, wh+WO_IH,wl+WO_IH,G3, gi,b_ih, NN,G3,FH, 0,0,0,nullptr);
        bt.total=bt.e[0].ntiles;
        k_bgemm<<<GB,T,SMEM_DYN>>>(bt);
    }
    k_gru<<<((size_t)NN*FH+T-1)/T,T>>>(gi,gh,hprev,out);
}

// round 12
// speedup vs baseline: 2.3574x; 1.2735x over previous
#include <cuda_runtime.h>
#include <cuda_bf16.h>
#include <mma.h>
#include <math.h>
#include <stdint.h>
using namespace nvcuda;

#define NN 20000
#define EE 320000
#define FIN 128
#define FH 256
#define RR 4
#define NH 4
#define G3 (3*FH)

#define OFF_AGG   ((size_t)0)
#define OFF_H1    (OFF_AGG + (size_t)NN*RR*FH)
#define OFF_H2    (OFF_H1  + (size_t)NN*FH)
#define OFF_Q     (OFF_H2  + (size_t)NN*FH)
#define OFF_K     (OFF_Q   + (size_t)NN*FH)
#define OFF_V     (OFF_K   + (size_t)NN*FH)
#define OFF_ATTN  (OFF_V   + (size_t)NN*FH)
#define OFF_SCORE (OFF_ATTN+ (size_t)NN*FH)
#define OFF_GHX   (OFF_SCORE+(size_t)EE*NH)
#define POOL_SZ   (OFF_GHX + (size_t)NN*G3)
#define OFF_GI    OFF_AGG

__device__ float g_pool[POOL_SZ];
__device__ float g_cnt[NN*RR];
__device__ int   g_smax[NN*NH];
__device__ float g_denom[NN*NH];
__device__ int   g_ticks[4];

// bf16 hi/lo weights, row-major [K][N]
#define WTOT 1146880
__device__ __align__(16) __nv_bfloat16 g_wh[WTOT];
__device__ __align__(16) __nv_bfloat16 g_wl[WTOT];
#define WO_W1 0
#define WO_W2 131072
#define WO_R1 393216
#define WO_R2 425984
#define WO_Q  491520
#define WO_KW 557056
#define WO_VW 622592
#define WO_SK 688128
#define WO_IH 753664
#define WO_HH 950272

__device__ __forceinline__ int f2oi(float f){ int i=__float_as_int(f); return i>=0?i:i^0x7fffffff; }
__device__ __forceinline__ float oi2f(int i){ return __int_as_float(i>=0?i:i^0x7fffffff); }
__device__ __forceinline__ float sigm(float x){ return 1.f/(1.f+expf(-x)); }
__device__ __forceinline__ float4 f4relu(float4 v){ return make_float4(fmaxf(v.x,0.f),fmaxf(v.y,0.f),fmaxf(v.z,0.f),fmaxf(v.w,0.f)); }
__device__ __forceinline__ float4 f4s(float4 v,float s){ return make_float4(v.x*s,v.y*s,v.z*s,v.w*s); }
// vector atomic add: one red.v4 instruction per 16B (sm_90+)
__device__ __forceinline__ void red4(float* p, float4 v){
    asm volatile("red.global.add.v4.f32 [%0], {%1,%2,%3,%4};"
                 :: "l"(p), "f"(v.x), "f"(v.y), "f"(v.z), "f"(v.w) : "memory");
}

__global__ void k_zero_f4(float4* p, size_t n4){
    for(size_t i=(size_t)blockIdx.x*blockDim.x+threadIdx.x;i<n4;i+=(size_t)gridDim.x*blockDim.x)
        p[i]=make_float4(0.f,0.f,0.f,0.f);
}
__global__ void k_tick0(){ if(threadIdx.x<4) g_ticks[threadIdx.x]=0; }
__global__ void k_seed_bias(float* C, const float* bias, int M, int N){
    size_t tot=(size_t)M*N;
    for(size_t i=(size_t)blockIdx.x*blockDim.x+threadIdx.x;i<tot;i+=(size_t)gridDim.x*blockDim.x) C[i]=bias[i%(size_t)N];
}
__global__ void k_init_attn(int* smax, float* denom, int n){
    int v=f2oi(-3.402823466e38f);
    for(int i=blockIdx.x*blockDim.x+threadIdx.x;i<n;i+=gridDim.x*blockDim.x){ smax[i]=v; denom[i]=0.f; }
}
__global__ void k_count(const int* __restrict__ dst, const int* __restrict__ et, float* cnt, int E){
    for(int e=blockIdx.x*blockDim.x+threadIdx.x;e<E;e+=gridDim.x*blockDim.x) atomicAdd(&cnt[dst[e]*RR+et[e]],1.f);
}
__global__ void k_scatter(const float* __restrict__ x, const int* __restrict__ src, const int* __restrict__ dst,
                          const int* __restrict__ et, float* __restrict__ agg, int E, int F, int relu){
    int g=blockIdx.x*blockDim.x+threadIdx.x, w=g>>5, l=g&31, nw=(gridDim.x*blockDim.x)>>5, F4=F>>2;
    for(int e=w;e<E;e+=nw){
        int s=src[e], d=dst[e], r=et[e];
        const float4* xs=(const float4*)(x+(size_t)s*F);
        float* ag=agg+((size_t)d*RR+r)*F;
        for(int i=l;i<F4;i+=32){
            float4 v=xs[i]; if(relu) v=f4relu(v);
            red4(ag+4*i, v);
        }
    }
}
__global__ void k_score(const float* __restrict__ q, const float* __restrict__ kk, const int* __restrict__ src,
                        const int* __restrict__ dst, float* __restrict__ score, int* __restrict__ smax, int E){
    int g=blockIdx.x*blockDim.x+threadIdx.x, w=g>>5, l=g&31, nw=(gridDim.x*blockDim.x)>>5;
    for(int e=w;e<E;e+=nw){
        int s=src[e], d=dst[e];
        const float4* qd=(const float4*)(q+(size_t)d*FH);
        const float4* ks=(const float4*)(kk+(size_t)s*FH);
        float4 a0=qd[l],b0=ks[l],a1=qd[l+32],b1=ks[l+32];
        float p0=a0.x*b0.x+a0.y*b0.y+a0.z*b0.z+a0.w*b0.w;
        float p1=a1.x*b1.x+a1.y*b1.y+a1.z*b1.z+a1.w*b1.w;
        #pragma unroll
        for(int o=8;o>=1;o>>=1){ p0+=__shfl_xor_sync(~0u,p0,o); p1+=__shfl_xor_sync(~0u,p1,o); }
        if((l&15)==0){
            int h=l>>4; float s0=p0*0.125f,s1=p1*0.125f;
            score[(size_t)e*NH+h]=s0; score[(size_t)e*NH+h+2]=s1;
            atomicMax(&smax[d*NH+h],f2oi(s0)); atomicMax(&smax[d*NH+h+2],f2oi(s1));
        }
    }
}
__global__ void k_expsum(float* __restrict__ score, const int* __restrict__ dst, const int* __restrict__ smax,
                         float* __restrict__ denom, int E){
    int tot=E*NH;
    for(int i=blockIdx.x*blockDim.x+threadIdx.x;i<tot;i+=gridDim.x*blockDim.x){
        int e=i>>2,h=i&3,d=dst[e];
        float ex=expf(score[i]-oi2f(smax[d*NH+h]));
        score[i]=ex; atomicAdd(&denom[d*NH+h],ex);
    }
}
__global__ void k_attn(const float* __restrict__ score, const float* __restrict__ denom, const float* __restrict__ v,
                       const int* __restrict__ src, const int* __restrict__ dst, float* __restrict__ out, int E){
    int g=blockIdx.x*blockDim.x+threadIdx.x, w=g>>5, l=g&31, nw=(gridDim.x*blockDim.x)>>5;
    for(int e=w;e<E;e+=nw){
        int s=src[e], d=dst[e], h0=l>>4;
        float a0=score[(size_t)e*NH+h0]/fmaxf(denom[d*NH+h0],1e-16f);
        float a1=score[(size_t)e*NH+h0+2]/fmaxf(denom[d*NH+h0+2],1e-16f);
        const float4* vs=(const float4*)(v+(size_t)s*FH);
        float* od=out+(size_t)d*FH;
        red4(od+4*l,      f4s(vs[l],a0));
        red4(od+4*(l+32), f4s(vs[l+32],a1));
    }
}
__global__ void k_gru(const float* __restrict__ gi, const float* __restrict__ gh, const float* __restrict__ hp, float* __restrict__ out){
    size_t tot=(size_t)NN*FH;
    for(size_t i=(size_t)blockIdx.x*blockDim.x+threadIdx.x;i<tot;i+=(size_t)gridDim.x*blockDim.x){
        size_t n=i/FH; int j=(int)(i%FH);
        const float* a=gi+n*G3; const float* b=gh+n*G3;
        float r=sigm(a[j]+b[j]), z=sigm(a[FH+j]+b[FH+j]);
        float nw=tanhf(a[2*FH+j]+r*b[2*FH+j]);
        out[i]=(1.f-z)*nw+z*hp[i];
    }
}

// fp32 weights -> bf16 hi/lo row-major [K][N]; trans: input is [N][K]
struct WEnt{ const float* W; __nv_bfloat16* dh; __nv_bfloat16* dl; int K,N,trans; };
struct WTab{ int tot; WEnt e[10]; int off[11]; };
__global__ void k_wconv(WTab t){
    int stride=gridDim.x*blockDim.x;
    for(int i=blockIdx.x*blockDim.x+threadIdx.x;i<t.tot;i+=stride){
        int g=0; while(i>=t.off[g+1]) g++;
        WEnt E=t.e[g]; int li=i-t.off[g];
        float w;
        if(!E.trans) w = E.W[li];
        else { int k=li/E.N, n=li-k*E.N; w = E.W[(size_t)n*E.K+k]; }
        __nv_bfloat16 hi=__float2bfloat16_rn(w);
        E.dh[li]=hi;
        E.dl[li]=__float2bfloat16_rn(w-__bfloat162float(hi));
    }
}

// ---------- persistent batched WMMA bf16 GEMM (3-term split) ----------------
struct Entry{
    const float* A; const __nv_bfloat16* Bh; const __nv_bfloat16* Bl;
    const float* bias; const float* cnt; float* C;
    int M,N,K,lda,ldb, atomic_ep, mode, rr, tiles_n, ntiles;
};
struct Batch{ int ng,total,slot; Entry e[6]; };

#define ALD 24
#define BLD 144
#define A_ELEMS (2*128*ALD)
#define B_ELEMS (2*16*BLD)
#define SMEM_DYN 65536

__global__ __launch_bounds__(256,2) void k_bgemm(Batch bt){
    extern __shared__ char sm[];
    __nv_bfloat16* Ah = (__nv_bfloat16*)sm;
    __nv_bfloat16* Al = Ah + A_ELEMS;
    __nv_bfloat16* Bhs = Al + A_ELEMS;
    __nv_bfloat16* Bls = Bhs + B_ELEMS;
    float* eps = (float*)sm;
    __shared__ int s_t;
    const int tid=threadIdx.x, wid=tid>>5, lid=tid&31;
    const int wr=wid>>1, wc=wid&1;
    const int arow=tid>>1, ak=(tid&1)*8;
    const int brow=tid>>4, bc=(tid&15)*8;

    for(;;){
        if(tid==0) s_t=atomicAdd(&g_ticks[bt.slot],1);
        __syncthreads();
        int t=s_t; if(t>=bt.total) return;
        int g=0,base=0;
        while(t>=base+bt.e[g].ntiles){ base+=bt.e[g].ntiles; g++; }
        const Entry E=bt.e[g];
        int lt=t-base, tm=lt/E.tiles_n, tn=lt-tm*E.tiles_n, m0=tm*128, n0=tn*128;

        wmma::fragment<wmma::accumulator,16,16,16,float> acc[2][4];
        #pragma unroll
        for(int i=0;i<2;i++)
            #pragma unroll
            for(int j=0;j<4;j++) wmma::fill_fragment(acc[i][j],0.f);

        const bool aok=(m0+arow<E.M);
        const float* abase = E.A + (size_t)(m0+arow)*E.lda + ak;
        float asc=1.f;
        if(E.mode==2) asc = aok ? 1.f/fmaxf(E.cnt[(m0+arow)*RR+E.rr],1.f) : 0.f;
        const __nv_bfloat16* bhg = E.Bh + (size_t)brow*E.ldb + n0 + bc;
        const __nv_bfloat16* blg = E.Bl + (size_t)brow*E.ldb + n0 + bc;

        float4 fa0,fa1; uint4 rbh,rbl;
        #define LOADT(k0) do{                                                   \
            if(aok){ fa0=*(const float4*)(abase+(k0)); fa1=*(const float4*)(abase+(k0)+4); \
                     if(E.mode==1){ fa0=f4relu(fa0); fa1=f4relu(fa1); }          \
                     else if(E.mode==2){ fa0=f4s(fa0,asc); fa1=f4s(fa1,asc); } } \
            else { fa0=make_float4(0,0,0,0); fa1=fa0; }                          \
            rbh=*(const uint4*)(bhg+(size_t)(k0)*E.ldb);                         \
            rbl=*(const uint4*)(blg+(size_t)(k0)*E.ldb);                         \
        }while(0)

        #define STORET(b) do{                                                    \
            __nv_bfloat16* ph=Ah+(b)*128*ALD+arow*ALD+ak;                        \
            __nv_bfloat16* pl=Al+(b)*128*ALD+arow*ALD+ak;                        \
            float fv[8]={fa0.x,fa0.y,fa0.z,fa0.w,fa1.x,fa1.y,fa1.z,fa1.w};       \
            _Pragma("unroll")                                                    \
            for(int u=0;u<8;u++){                                                \
                __nv_bfloat16 h=__float2bfloat16_rn(fv[u]);                      \
                ph[u]=h; pl[u]=__float2bfloat16_rn(fv[u]-__bfloat162float(h));   \
            }                                                                    \
            *(uint4*)(Bhs+(b)*16*BLD+brow*BLD+bc)=rbh;                           \
            *(uint4*)(Bls+(b)*16*BLD+brow*BLD+bc)=rbl;                           \
        }while(0)

        #define COMPUTE(b) do{                                                   \
            const __nv_bfloat16* pa_h=Ah+(b)*128*ALD+(wr*32)*ALD;                \
            const __nv_bfloat16* pa_l=Al+(b)*128*ALD+(wr*32)*ALD;                \
            const __nv_bfloat16* pb_h=Bhs+(b)*16*BLD+wc*64;                      \
            const __nv_bfloat16* pb_l=Bls+(b)*16*BLD+wc*64;                      \
            wmma::fragment<wmma::matrix_a,16,16,16,__nv_bfloat16,wmma::row_major> ah[2],al2[2]; \
            wmma::fragment<wmma::matrix_b,16,16,16,__nv_bfloat16,wmma::row_major> bh[4],bl2[4]; \
            _Pragma("unroll")                                                    \
            for(int i=0;i<2;i++){ wmma::load_matrix_sync(ah[i],pa_h+i*16*ALD,ALD); \
                                  wmma::load_matrix_sync(al2[i],pa_l+i*16*ALD,ALD); } \
            _Pragma("unroll")                                                    \
            for(int j=0;j<4;j++){ wmma::load_matrix_sync(bh[j],pb_h+j*16,BLD);   \
                                  wmma::load_matrix_sync(bl2[j],pb_l+j*16,BLD); } \
            _Pragma("unroll")                                                    \
            for(int i=0;i<2;i++)                                                 \
                _Pragma("unroll")                                                \
                for(int j=0;j<4;j++){                                            \
                    wmma::mma_sync(acc[i][j],ah[i],bh[j],acc[i][j]);             \
                    wmma::mma_sync(acc[i][j],al2[i],bh[j],acc[i][j]);            \
                    wmma::mma_sync(acc[i][j],ah[i],bl2[j],acc[i][j]);            \
                }                                                                \
        }while(0)

        LOADT(0); STORET(0);
        __syncthreads();
        int buf=0;
        for(int k0=16;k0<E.K;k0+=16){
            LOADT(k0);
            COMPUTE(buf);
            STORET(buf^1);
            __syncthreads();
            buf^=1;
        }
        COMPUTE(buf);
        __syncthreads();
        #undef LOADT
        #undef STORET
        #undef COMPUTE

        // epilogue: per-warp 32x64 region via smem
        float* ep = eps + wid*2048;
        #pragma unroll
        for(int i=0;i<2;i++)
            #pragma unroll
            for(int j=0;j<4;j++)
                wmma::store_matrix_sync(ep + i*16*64 + j*16, acc[i][j], 64, wmma::mem_row_major);
        __syncwarp();
        int c0 = n0 + wc*64 + lid*2;
        for(int r2=0;r2<32;r2++){
            int row = m0 + wr*32 + r2;
            if(row >= E.M) break;
            float v0=ep[r2*64+lid*2], v1=ep[r2*64+lid*2+1];
            float* crow = E.C + (size_t)row*E.N + c0;
            if(E.atomic_ep){ atomicAdd(crow,v0); atomicAdd(crow+1,v1); }
            else { crow[0]=v0+E.bias[c0]; crow[1]=v1+E.bias[c0+1]; }
        }
        __syncthreads();
    }
}

static Entry mkent(const float* A,int lda,const __nv_bfloat16* bh,const __nv_bfloat16* bl,int ldb,
                   float* C,const float* bias,int M,int N,int K,int atomic_ep,int mode,int rr,const float* cnt){
    Entry e; e.A=A; e.Bh=bh; e.Bl=bl; e.bias=bias; e.cnt=cnt; e.C=C;
    e.M=M; e.N=N; e.K=K; e.lda=lda; e.ldb=ldb;
    e.atomic_ep=atomic_ep; e.mode=mode; e.rr=rr;
    e.tiles_n=N/128; e.ntiles=((M+127)/128)*e.tiles_n;
    return e;
}

extern "C" void kernel_launch(void* const* d_in, const int* in_sizes, int n_in, void* d_out, int out_size){
    const float* x=(const float*)d_in[0];
    const int* eidx=(const int*)d_in[1];
    const int* src=eidx; const int* dst=eidx+EE;
    const int* et=(const int*)d_in[2];
    const float* hprev=(const float*)d_in[3];
    const float* W1=(const float*)d_in[4];   const float* root1=(const float*)d_in[5];  const float* b1=(const float*)d_in[6];
    const float* W2=(const float*)d_in[7];   const float* root2=(const float*)d_in[8];  const float* b2=(const float*)d_in[9];
    const float* Wq=(const float*)d_in[10];  const float* bq=(const float*)d_in[11];
    const float* Wk=(const float*)d_in[12];  const float* bk=(const float*)d_in[13];
    const float* Wv=(const float*)d_in[14];  const float* bv=(const float*)d_in[15];
    const float* Wskip=(const float*)d_in[16]; const float* bskip=(const float*)d_in[17];
    const float* W_ih=(const float*)d_in[18]; const float* b_ih=(const float*)d_in[19];
    const float* W_hh=(const float*)d_in[20]; const float* b_hh=(const float*)d_in[21];
    float* out=(float*)d_out;

    static float* pool=nullptr; static float* cnt; static int* smax; static float* denom;
    static __nv_bfloat16 *wh,*wl;
    if(!pool){
        void* p;
        cudaGetSymbolAddress(&p,g_pool); pool=(float*)p;
        cudaGetSymbolAddress(&p,g_cnt); cnt=(float*)p;
        cudaGetSymbolAddress(&p,g_smax); smax=(int*)p;
        cudaGetSymbolAddress(&p,g_denom); denom=(float*)p;
        cudaGetSymbolAddress(&p,g_wh); wh=(__nv_bfloat16*)p;
        cudaGetSymbolAddress(&p,g_wl); wl=(__nv_bfloat16*)p;
        cudaFuncSetAttribute(k_bgemm, cudaFuncAttributeMaxDynamicSharedMemorySize, SMEM_DYN);
    }
    float* agg=pool+OFF_AGG; float* h1=pool+OFF_H1; float* h2=pool+OFF_H2;
    float* q=pool+OFF_Q; float* k=pool+OFF_K; float* v=pool+OFF_V;
    float* attn=pool+OFF_ATTN; float* score=pool+OFF_SCORE;
    float* gh=pool+OFF_GHX; float* gi=pool+OFF_GI;

    const int T=256, GB=304;
    int eW=(EE*32+T-1)/T;

    k_tick0<<<1,32>>>();
    { // weight conversion
        WTab wt; int idx=0; int sz[10];
        auto add=[&](const float* W,int K,int N,int tr,int off){ wt.e[idx]=WEnt{W,wh+off,wl+off,K,N,tr}; sz[idx]=N*K; idx++; };
        add(W1,512,256,0,WO_W1);
        add(W2,1024,256,0,WO_W2);
        add(root1,128,256,0,WO_R1);
        add(root2,256,256,0,WO_R2);
        add(Wq,256,256,0,WO_Q); add(Wk,256,256,0,WO_KW); add(Wv,256,256,0,WO_VW); add(Wskip,256,256,0,WO_SK);
        add(W_ih,256,768,1,WO_IH); add(W_hh,256,768,1,WO_HH);
        wt.off[0]=0; for(int i=0;i<10;i++) wt.off[i+1]=wt.off[i]+sz[i];
        wt.tot=wt.off[10];
        k_wconv<<<2048,T>>>(wt);
    }
    k_zero_f4<<<(NN*RR/4+T-1)/T,T>>>((float4*)cnt,(size_t)NN*RR/4);
    k_count<<<(EE+T-1)/T,T>>>(dst,et,cnt,EE);

    k_zero_f4<<<2048,T>>>((float4*)agg,(size_t)NN*RR*FIN/4);
    k_scatter<<<eW,T>>>(x,src,dst,et,agg,EE,FIN,0);
    k_seed_bias<<<1024,T>>>(h1,b1,NN,FH);
    { // batch 1: RGCN1 (root + 4 relations, atomic) + gh
        Batch bt; bt.slot=0; bt.ng=6;
        bt.e[0]=mkent(x,FIN, wh+WO_R1,wl+WO_R1,FH, h1,nullptr, NN,FH,FIN, 1,0,0,nullptr);
        for(int r=0;r<RR;r++)
            bt.e[1+r]=mkent(agg+r*FIN,RR*FIN, wh+WO_W1+r*FIN*FH,wl+WO_W1+r*FIN*FH,FH,
                            h1,nullptr, NN,FH,FIN, 1,2,r,cnt);
        bt.e[5]=mkent(hprev,FH, wh+WO_HH,wl+WO_HH,G3, gh,b_hh, NN,G3,FH, 0,0,0,nullptr);
        bt.total=0; for(int i=0;i<bt.ng;i++) bt.total+=bt.e[i].ntiles;
        k_bgemm<<<GB,T,SMEM_DYN>>>(bt);
    }
    k_zero_f4<<<4096,T>>>((float4*)agg,(size_t)NN*RR*FH/4);
    k_scatter<<<eW,T>>>(h1,src,dst,et,agg,EE,FH,1);
    k_seed_bias<<<1024,T>>>(h2,b2,NN,FH);
    { // batch 2: RGCN2
        Batch bt; bt.slot=1; bt.ng=5;
        bt.e[0]=mkent(h1,FH, wh+WO_R2,wl+WO_R2,FH, h2,nullptr, NN,FH,FH, 1,1,0,nullptr);
        for(int r=0;r<RR;r++)
            bt.e[1+r]=mkent(agg+r*FH,RR*FH, wh+WO_W2+r*FH*FH,wl+WO_W2+r*FH*FH,FH,
                            h2,nullptr, NN,FH,FH, 1,2,r,cnt);
        bt.total=0; for(int i=0;i<bt.ng;i++) bt.total+=bt.e[i].ntiles;
        k_bgemm<<<GB,T,SMEM_DYN>>>(bt);
    }
    { // batch 3: q/k/v/skip
        Batch bt; bt.slot=2; bt.ng=4;
        bt.e[0]=mkent(h2,FH, wh+WO_Q, wl+WO_Q, FH, q,   bq,   NN,FH,FH, 0,1,0,nullptr);
        bt.e[1]=mkent(h2,FH, wh+WO_KW,wl+WO_KW,FH, k,   bk,   NN,FH,FH, 0,1,0,nullptr);
        bt.e[2]=mkent(h2,FH, wh+WO_VW,wl+WO_VW,FH, v,   bv,   NN,FH,FH, 0,1,0,nullptr);
        bt.e[3]=mkent(h2,FH, wh+WO_SK,wl+WO_SK,FH, attn,bskip,NN,FH,FH, 0,1,0,nullptr);
        bt.total=0; for(int i=0;i<bt.ng;i++) bt.total+=bt.e[i].ntiles;
        k_bgemm<<<GB,T,SMEM_DYN>>>(bt);
    }
    k_init_attn<<<(NN*NH+T-1)/T,T>>>(smax,denom,NN*NH);
    k_score<<<eW,T>>>(q,k,src,dst,score,smax,EE);
    k_expsum<<<(EE*NH+T-1)/T,T>>>(score,dst,smax,denom,EE);
    k_attn<<<eW,T>>>(score,denom,v,src,dst,attn,EE);
    { // batch 4: gi
        Batch bt; bt.slot=3; bt.ng=1;
        bt.e[0]=mkent(attn,FH, wh+WO_IH,wl+WO_IH,G3, gi,b_ih, NN,G3,FH, 0,0,0,nullptr);
        bt.total=bt.e[0].ntiles;
        k_bgemm<<<GB,T,SMEM_DYN>>>(bt);
    }
    k_gru<<<((size_t)NN*FH+T-1)/T,T>>>(gi,gh,hprev,out);
}